// round 5
// baseline (speedup 1.0000x reference)
#include <cuda_runtime.h>
#include <cuda_bf16.h>
#include <cstdint>

#define EMBED 1024
#define HEAD  128
#define BATCH 4
#define SEQ   4096
#define BS    (BATCH*SEQ)
#define SCALE 0.03125f   // 1/sqrt(1024)

// ---------------------------------------------------------------------------
// Global scratch (bf16 hi/lo splits) + l accumulator
// ---------------------------------------------------------------------------
__device__ __align__(256) __nv_bfloat16 g_xh[BS*EMBED], g_xl[BS*EMBED];
__device__ __align__(256) __nv_bfloat16 g_wh[3*EMBED*HEAD], g_wl[3*EMBED*HEAD];
__device__ __align__(256) __nv_bfloat16 g_qh[BS*HEAD], g_ql[BS*HEAD];
__device__ __align__(256) __nv_bfloat16 g_kh[BS*HEAD], g_kl[BS*HEAD];
__device__ __align__(256) __nv_bfloat16 g_vh[BS*HEAD], g_vl[BS*HEAD];
__device__ __align__(256) float g_l[BS];

// ---------------------------------------------------------------------------
// helpers
// ---------------------------------------------------------------------------
__device__ __forceinline__ uint32_t smem_u32(const void* p) {
    uint32_t a;
    asm("{ .reg .u64 t; cvta.to.shared.u64 t, %1; cvt.u32.u64 %0, t; }" : "=r"(a) : "l"(p));
    return a;
}
__device__ __forceinline__ uint32_t sidx(int row, int cb, int rb) {
    return (uint32_t)(row*rb + ((((cb >> 4) ^ (row & 7)) << 4) | (cb & 15)));
}
__device__ __forceinline__ void cpa(uint32_t d, const void* s) {
    asm volatile("cp.async.cg.shared.global [%0], [%1], 16;" :: "r"(d), "l"(s));
}
#define CP_COMMIT() asm volatile("cp.async.commit_group;" ::: "memory")
#define CP_WAIT0()  asm volatile("cp.async.wait_group 0;" ::: "memory")
#define CP_WAIT1()  asm volatile("cp.async.wait_group 1;" ::: "memory")

__device__ __forceinline__ void ldsm4(uint32_t* r, uint32_t a) {
    asm volatile("ldmatrix.sync.aligned.m8n8.x4.shared.b16 {%0,%1,%2,%3}, [%4];"
        : "=r"(r[0]), "=r"(r[1]), "=r"(r[2]), "=r"(r[3]) : "r"(a));
}
__device__ __forceinline__ void ldsm4t(uint32_t* r, uint32_t a) {
    asm volatile("ldmatrix.sync.aligned.m8n8.x4.trans.shared.b16 {%0,%1,%2,%3}, [%4];"
        : "=r"(r[0]), "=r"(r[1]), "=r"(r[2]), "=r"(r[3]) : "r"(a));
}
__device__ __forceinline__ void mma16816(float* d, const uint32_t* a, const uint32_t* b) {
    asm volatile("mma.sync.aligned.m16n8k16.row.col.f32.bf16.bf16.f32 "
        "{%0,%1,%2,%3}, {%4,%5,%6,%7}, {%8,%9}, {%0,%1,%2,%3};"
        : "+f"(d[0]), "+f"(d[1]), "+f"(d[2]), "+f"(d[3])
        : "r"(a[0]), "r"(a[1]), "r"(a[2]), "r"(a[3]), "r"(b[0]), "r"(b[1]));
}
__device__ __forceinline__ void split2(float a, float b, uint32_t& hi, uint32_t& lo) {
    __nv_bfloat162 h = __float22bfloat162_rn(make_float2(a, b));
    float2 hf = __bfloat1622float2(h);
    __nv_bfloat162 l = __float22bfloat162_rn(make_float2(a - hf.x, b - hf.y));
    hi = *(uint32_t*)&h; lo = *(uint32_t*)&l;
}

// ---------------------------------------------------------------------------
// convert kernels: fp32 -> bf16 hi/lo
// ---------------------------------------------------------------------------
__global__ __launch_bounds__(256) void conv_x_kernel(const float* __restrict__ x)
{
    size_t i = ((size_t)blockIdx.x*256 + threadIdx.x)*4;
    float4 v = *(const float4*)(x + i);
    uint32_t h0, l0, h1, l1;
    split2(v.x, v.y, h0, l0);
    split2(v.z, v.w, h1, l1);
    *(uint2*)(g_xh + i) = make_uint2(h0, h1);
    *(uint2*)(g_xl + i) = make_uint2(l0, l1);
}
__global__ __launch_bounds__(256) void conv_w_kernel(
    const float* __restrict__ Wk, const float* __restrict__ Wq, const float* __restrict__ Wv)
{
    const int w = blockIdx.y;
    const float* W = (w == 0) ? Wq : (w == 1) ? Wk : Wv;
    size_t base = (size_t)w*EMBED*HEAD;
    size_t i = ((size_t)blockIdx.x*256 + threadIdx.x)*4;
    float4 v = *(const float4*)(W + i);
    uint32_t h0, l0, h1, l1;
    split2(v.x, v.y, h0, l0);
    split2(v.z, v.w, h1, l1);
    *(uint2*)(g_wh + base + i) = make_uint2(h0, h1);
    *(uint2*)(g_wl + base + i) = make_uint2(l0, l1);
}

// ---------------------------------------------------------------------------
// zero / normalize
// ---------------------------------------------------------------------------
__global__ __launch_bounds__(256) void zero_kernel(float* __restrict__ out)
{
    int bid = blockIdx.x;
    if (bid < 2048) {
        size_t i = ((size_t)bid*256 + threadIdx.x)*4;
        *(float4*)(out + i) = make_float4(0.f, 0.f, 0.f, 0.f);
    } else {
        size_t i = ((size_t)(bid - 2048)*256 + threadIdx.x)*4;
        *(float4*)(g_l + i) = make_float4(0.f, 0.f, 0.f, 0.f);
    }
}
__global__ __launch_bounds__(256) void norm_kernel(float* __restrict__ out)
{
    size_t i4 = (size_t)blockIdx.x*256 + threadIdx.x;
    int row = (int)(i4 >> 5);
    float inv = 1.f / g_l[row];
    float4 v = *(float4*)(out + i4*4);
    v.x *= inv; v.y *= inv; v.z *= inv; v.w *= inv;
    *(float4*)(out + i4*4) = v;
}

// ---------------------------------------------------------------------------
// Projection GEMM on HMMA: 512 threads (16 warps = 4/SMSP).
// Warps: 8 row-groups (16 rows) x 2 col-halves (64 cols). acc = 32 regs.
// smem/stage: XH 16K | XL 16K | WH 16K | WL 16K  (2 stages = 128KB)
// ---------------------------------------------------------------------------
#define PJ_STAGE 65536
#define PJ_SMEM  (2*PJ_STAGE)

__global__ __launch_bounds__(512, 1) void proj_kernel()
{
    extern __shared__ char sm[];
    const uint32_t smb = smem_u32(sm);
    const int tid = threadIdx.x, wid = tid >> 5, l = tid & 31;
    const int w = blockIdx.x;                 // weight index (fastest -> L2 share x)
    const int row0 = blockIdx.y * 128;
    const int rg = wid & 7;                   // row group (16 rows)
    const int ch = wid >> 3;                  // col half  (64 cols)

    const __nv_bfloat16* xh = g_xh + (size_t)row0*EMBED;
    const __nv_bfloat16* xl = g_xl + (size_t)row0*EMBED;
    const __nv_bfloat16* wh = g_wh + (size_t)w*EMBED*HEAD;
    const __nv_bfloat16* wl = g_wl + (size_t)w*EMBED*HEAD;

    auto load_stage = [&](int s, int k0) {
        uint32_t sb = smb + s*PJ_STAGE;
        #pragma unroll
        for (int i = 0; i < 2; i++) {               // x tiles [128][64]
            int f = i*512 + tid;
            int r = f >> 3, c = f & 7;
            uint32_t d = sb + sidx(r, c*16, 128);
            cpa(d,         xh + (size_t)r*EMBED + k0 + c*8);
            cpa(d + 16384, xl + (size_t)r*EMBED + k0 + c*8);
        }
        #pragma unroll
        for (int i = 0; i < 2; i++) {               // W tiles [64][128]
            int f = i*512 + tid;
            int r = f >> 4, c = f & 15;
            uint32_t d = sb + 32768 + sidx(r, c*16, 256);
            cpa(d,         wh + (size_t)(k0 + r)*HEAD + c*8);
            cpa(d + 16384, wl + (size_t)(k0 + r)*HEAD + c*8);
        }
        CP_COMMIT();
    };

    float acc[8][4];
    #pragma unroll
    for (int n = 0; n < 8; n++)
        #pragma unroll
        for (int j = 0; j < 4; j++) acc[n][j] = 0.f;

    load_stage(0, 0);

    for (int chk = 0; chk < 16; chk++) {
        int cur = chk & 1;
        if (chk + 1 < 16) { load_stage(cur ^ 1, (chk + 1)*64); CP_WAIT1(); }
        else              { CP_WAIT0(); }
        __syncthreads();

        uint32_t sb = smb + cur*PJ_STAGE;
        #pragma unroll
        for (int ks = 0; ks < 4; ks++) {
            uint32_t ah[4], al[4];
            uint32_t aoff = sidx(rg*16 + (l & 15), ks*32 + ((l >> 4) << 4), 128);
            ldsm4(ah, sb + aoff);
            ldsm4(al, sb + 16384 + aoff);
            #pragma unroll
            for (int ntp = 0; ntp < 4; ntp++) {
                int nt0 = ntp*2;
                uint32_t bh[4], bl[4];
                uint32_t boff = sidx(ks*16 + (l & 15),
                                     ch*128 + nt0*16 + ((l >> 4) & 1)*16, 256);
                ldsm4t(bh, sb + 32768 + boff);
                ldsm4t(bl, sb + 49152 + boff);
                mma16816(acc[nt0],   ah, bh);
                mma16816(acc[nt0],   ah, bl);
                mma16816(acc[nt0],   al, bh);
                mma16816(acc[nt0+1], ah, bh + 2);
                mma16816(acc[nt0+1], ah, bl + 2);
                mma16816(acc[nt0+1], al, bh + 2);
            }
        }
        __syncthreads();
    }

    __nv_bfloat16* dh = (w == 0) ? g_qh : (w == 1) ? g_kh : g_vh;
    __nv_bfloat16* dl = (w == 0) ? g_ql : (w == 1) ? g_kl : g_vl;
    const int g0 = row0 + rg*16 + (l >> 2);
    const int cb = ch*64 + (l & 3)*2;
    #pragma unroll
    for (int nt = 0; nt < 8; nt++) {
        uint32_t h, lo;
        split2(acc[nt][0], acc[nt][1], h, lo);
        *(uint32_t*)(dh + (size_t)g0*HEAD + cb + nt*8) = h;
        *(uint32_t*)(dl + (size_t)g0*HEAD + cb + nt*8) = lo;
        split2(acc[nt][2], acc[nt][3], h, lo);
        *(uint32_t*)(dh + (size_t)(g0 + 8)*HEAD + cb + nt*8) = h;
        *(uint32_t*)(dl + (size_t)(g0 + 8)*HEAD + cb + nt*8) = lo;
    }
}

// ---------------------------------------------------------------------------
// Flash attention: 8 warps (2/SMSP), 64 queries, keys split across warp
// halves, split-KV chunks of 32 k-tiles across CTAs (additive partials).
// B operands via ldmatrix.x4 pairs (half the LDSM issues of R4).
// smem: QH 16K | QL 16K | 2 x stage{KH,KL,VH,VL each 16K} = 160KB
// ---------------------------------------------------------------------------
#define AT_KV0   32768
#define AT_STAGE 65536
#define AT_SMEM  (AT_KV0 + 2*AT_STAGE)
#define CHUNK    32   // k-tiles per CTA

__global__ __launch_bounds__(256, 1) void attn_kernel(float* __restrict__ out)
{
    const int qt = 63 - blockIdx.x;            // heavy q-tiles first
    const int c  = blockIdx.y;
    const int t0 = c*CHUNK;
    const int t1 = min(t0 + CHUNK, qt + 1);
    if (t0 >= t1) return;

    extern __shared__ char sm[];
    const uint32_t smb = smem_u32(sm);
    const int tid = threadIdx.x, wid = tid >> 5, l = tid & 31;
    const int b   = blockIdx.z;
    const int q0  = qt*64;
    const int wq  = (wid & 3)*16;              // query sub-tile
    const int kh  = wid >> 2;                  // key half (0/1)
    const bool single = (c == 0) && (qt + 1 <= CHUNK);

    // Q tiles (persistent); committed with first KV stage
    {
        const __nv_bfloat16* qh = g_qh + ((size_t)b*SEQ + q0)*HEAD;
        const __nv_bfloat16* ql = g_ql + ((size_t)b*SEQ + q0)*HEAD;
        #pragma unroll
        for (int i = 0; i < 4; i++) {
            int f = i*256 + tid;
            int r = f >> 4, cc = f & 15;
            uint32_t d = smb + sidx(r, cc*16, 256);
            cpa(d,         qh + (size_t)r*HEAD + cc*8);
            cpa(d + 16384, ql + (size_t)r*HEAD + cc*8);
        }
    }

    auto load_kv = [&](int s, int t) {
        uint32_t sb = smb + AT_KV0 + s*AT_STAGE;
        const size_t base = ((size_t)b*SEQ + t*64)*HEAD;
        #pragma unroll
        for (int i = 0; i < 4; i++) {
            int f = i*256 + tid;
            int r = f >> 4, cc = f & 15;
            uint32_t d = sb + sidx(r, cc*16, 256);
            const size_t g = base + (size_t)r*HEAD + cc*8;
            cpa(d,         g_kh + g);
            cpa(d + 16384, g_kl + g);
            cpa(d + 32768, g_vh + g);
            cpa(d + 49152, g_vl + g);
        }
        CP_COMMIT();
    };

    float o[16][4];
    #pragma unroll
    for (int n = 0; n < 16; n++)
        #pragma unroll
        for (int j = 0; j < 4; j++) o[n][j] = 0.f;
    float lsum0 = 0.f, lsum1 = 0.f;

    load_kv(0, t0);

    for (int t = t0; t < t1; t++) {
        int cur = (t - t0) & 1;
        if (t + 1 < t1) { load_kv(cur ^ 1, t + 1); CP_WAIT1(); }
        else            { CP_WAIT0(); }
        __syncthreads();

        uint32_t sb = smb + AT_KV0 + cur*AT_STAGE;

        // ---- scores S[16q x 32k] for this warp's key half ----
        float s[4][4];
        #pragma unroll
        for (int n = 0; n < 4; n++)
            #pragma unroll
            for (int j = 0; j < 4; j++) s[n][j] = 0.f;

        #pragma unroll
        for (int ks = 0; ks < 8; ks++) {
            uint32_t ah[4], al[4];
            uint32_t aoff = sidx(wq + (l & 15), ks*32 + ((l >> 4) << 4), 256);
            ldsm4(ah, smb + aoff);
            ldsm4(al, smb + 16384 + aoff);
            #pragma unroll
            for (int ntp = 0; ntp < 2; ntp++) {
                int nt0 = ntp*2;
                uint32_t bh[4], bl[4];
                uint32_t boff = sidx(kh*32 + (nt0 + ((l >> 4) & 1))*8 + (l & 7),
                                     ks*32 + ((l >> 3) & 1)*16, 256);
                ldsm4(bh, sb + boff);
                ldsm4(bl, sb + 16384 + boff);
                mma16816(s[nt0],   ah, bh);
                mma16816(s[nt0],   ah, bl);
                mma16816(s[nt0],   al, bh);
                mma16816(s[nt0+1], ah, bh + 2);
                mma16816(s[nt0+1], ah, bl + 2);
                mma16816(s[nt0+1], al, bh + 2);
            }
        }

        // ---- p = exp(s*scale), causal mask on diagonal tile ----
        uint32_t Ph[4][2], Pl[4][2];
        const bool diag = (t == qt);
        const int lq = q0 + wq + (l >> 2);
        #pragma unroll
        for (int nt = 0; nt < 4; nt++) {
            int kc = t*64 + kh*32 + nt*8 + (l & 3)*2;
            float p00 = __expf(s[nt][0]*SCALE);
            float p01 = __expf(s[nt][1]*SCALE);
            float p10 = __expf(s[nt][2]*SCALE);
            float p11 = __expf(s[nt][3]*SCALE);
            if (diag) {
                if (kc     > lq)     p00 = 0.f;
                if (kc + 1 > lq)     p01 = 0.f;
                if (kc     > lq + 8) p10 = 0.f;
                if (kc + 1 > lq + 8) p11 = 0.f;
            }
            lsum0 += p00 + p01;
            lsum1 += p10 + p11;
            split2(p00, p01, Ph[nt][0], Pl[nt][0]);
            split2(p10, p11, Ph[nt][1], Pl[nt][1]);
        }

        // ---- O += P * V over this warp's 32 keys ----
        #pragma unroll
        for (int ks = 0; ks < 2; ks++) {
            uint32_t ahh[4] = {Ph[2*ks][0], Ph[2*ks][1], Ph[2*ks+1][0], Ph[2*ks+1][1]};
            uint32_t all[4] = {Pl[2*ks][0], Pl[2*ks][1], Pl[2*ks+1][0], Pl[2*ks+1][1]};
            #pragma unroll
            for (int ntp = 0; ntp < 8; ntp++) {
                int nt0 = ntp*2;
                uint32_t bh[4], bl[4];
                uint32_t boff = sidx(kh*32 + ks*16 + (l & 15),
                                     nt0*16 + ((l >> 4) & 1)*16, 256);
                ldsm4t(bh, sb + 32768 + boff);
                ldsm4t(bl, sb + 49152 + boff);
                mma16816(o[nt0],   ahh, bh);
                mma16816(o[nt0],   ahh, bl);
                mma16816(o[nt0],   all, bh);
                mma16816(o[nt0+1], ahh, bh + 2);
                mma16816(o[nt0+1], ahh, bl + 2);
                mma16816(o[nt0+1], all, bh + 2);
            }
        }
        __syncthreads();
    }

    // ---- cross-half reduction via smem (warps w and w+4 share queries) ----
    if (wid >= 4) {
        float* red = (float*)(sm + AT_KV0) + ((size_t)((wid - 4)*32 + l))*64;
        #pragma unroll
        for (int nt = 0; nt < 16; nt++)
            *(float4*)(red + nt*4) = make_float4(o[nt][0], o[nt][1], o[nt][2], o[nt][3]);
        float* lred = (float*)(sm + AT_KV0 + 32768) + ((wid - 4)*32 + l)*2;
        lred[0] = lsum0; lred[1] = lsum1;
    }
    __syncthreads();
    if (wid < 4) {
        float* red = (float*)(sm + AT_KV0) + ((size_t)(wid*32 + l))*64;
        #pragma unroll
        for (int nt = 0; nt < 16; nt++) {
            float4 r = *(float4*)(red + nt*4);
            o[nt][0] += r.x; o[nt][1] += r.y; o[nt][2] += r.z; o[nt][3] += r.w;
        }
        float* lred = (float*)(sm + AT_KV0 + 32768) + (wid*32 + l)*2;
        lsum0 += lred[0]; lsum1 += lred[1];

        lsum0 += __shfl_xor_sync(0xffffffffu, lsum0, 1);
        lsum0 += __shfl_xor_sync(0xffffffffu, lsum0, 2);
        lsum1 += __shfl_xor_sync(0xffffffffu, lsum1, 1);
        lsum1 += __shfl_xor_sync(0xffffffffu, lsum1, 2);

        const int row0g = q0 + wq + (l >> 2);
        const int cb = (l & 3)*2;
        float* og = out + ((size_t)b*SEQ + row0g)*HEAD;

        if (single) {
            #pragma unroll
            for (int nt = 0; nt < 16; nt++) {
                *(float2*)(og + nt*8 + cb) = make_float2(o[nt][0], o[nt][1]);
                *(float2*)(og + (size_t)8*HEAD + nt*8 + cb) = make_float2(o[nt][2], o[nt][3]);
            }
            if ((l & 3) == 0) {
                g_l[b*SEQ + row0g]     = lsum0;
                g_l[b*SEQ + row0g + 8] = lsum1;
            }
        } else {
            #pragma unroll
            for (int nt = 0; nt < 16; nt++) {
                atomicAdd(og + nt*8 + cb,     o[nt][0]);
                atomicAdd(og + nt*8 + cb + 1, o[nt][1]);
                atomicAdd(og + (size_t)8*HEAD + nt*8 + cb,     o[nt][2]);
                atomicAdd(og + (size_t)8*HEAD + nt*8 + cb + 1, o[nt][3]);
            }
            if ((l & 3) == 0) {
                atomicAdd(g_l + b*SEQ + row0g,     lsum0);
                atomicAdd(g_l + b*SEQ + row0g + 8, lsum1);
            }
        }
    }
}

// ---------------------------------------------------------------------------
extern "C" void kernel_launch(void* const* d_in, const int* in_sizes, int n_in,
                              void* d_out, int out_size)
{
    const float* x  = (const float*)d_in[0];
    const float* Wk = (const float*)d_in[1];
    const float* Wq = (const float*)d_in[2];
    const float* Wv = (const float*)d_in[3];
    float* out = (float*)d_out;

    cudaFuncSetAttribute(proj_kernel, cudaFuncAttributeMaxDynamicSharedMemorySize, PJ_SMEM);
    cudaFuncSetAttribute(attn_kernel, cudaFuncAttributeMaxDynamicSharedMemorySize, AT_SMEM);

    zero_kernel<<<2064, 256>>>(out);
    conv_x_kernel<<<BS*EMBED/1024, 256>>>(x);
    conv_w_kernel<<<dim3(EMBED*HEAD/1024, 3), 256>>>(Wk, Wq, Wv);
    proj_kernel<<<dim3(3, BS/128), 512, PJ_SMEM>>>();
    attn_kernel<<<dim3(64, (SEQ/64 + CHUNK - 1)/CHUNK, BATCH), 256, AT_SMEM>>>(out);
    norm_kernel<<<BS*HEAD/1024, 256>>>(out);
}

// round 6
// speedup vs baseline: 1.0136x; 1.0136x over previous
#include <cuda_runtime.h>
#include <cuda_bf16.h>
#include <cstdint>

#define EMBED 1024
#define HEAD  128
#define BATCH 4
#define SEQ   4096
#define BS    (BATCH*SEQ)
#define SCALE 0.03125f   // 1/sqrt(1024)

// ---------------------------------------------------------------------------
// Global scratch (bf16 hi/lo splits) + l accumulator
// ---------------------------------------------------------------------------
__device__ __align__(256) __nv_bfloat16 g_xh[BS*EMBED], g_xl[BS*EMBED];
__device__ __align__(256) __nv_bfloat16 g_wh[3*EMBED*HEAD], g_wl[3*EMBED*HEAD];
__device__ __align__(256) __nv_bfloat16 g_qh[BS*HEAD], g_ql[BS*HEAD];
__device__ __align__(256) __nv_bfloat16 g_kh[BS*HEAD], g_kl[BS*HEAD];
__device__ __align__(256) __nv_bfloat16 g_vh[BS*HEAD], g_vl[BS*HEAD];
__device__ __align__(256) float g_l[BS];

// ---------------------------------------------------------------------------
// helpers
// ---------------------------------------------------------------------------
__device__ __forceinline__ uint32_t smem_u32(const void* p) {
    uint32_t a;
    asm("{ .reg .u64 t; cvta.to.shared.u64 t, %1; cvt.u32.u64 %0, t; }" : "=r"(a) : "l"(p));
    return a;
}
__device__ __forceinline__ uint32_t sidx(int row, int cb, int rb) {
    return (uint32_t)(row*rb + ((((cb >> 4) ^ (row & 7)) << 4) | (cb & 15)));
}
__device__ __forceinline__ void cpa(uint32_t d, const void* s) {
    asm volatile("cp.async.cg.shared.global [%0], [%1], 16;" :: "r"(d), "l"(s));
}
#define CP_COMMIT() asm volatile("cp.async.commit_group;" ::: "memory")
#define CP_WAIT0()  asm volatile("cp.async.wait_group 0;" ::: "memory")
#define CP_WAIT1()  asm volatile("cp.async.wait_group 1;" ::: "memory")

__device__ __forceinline__ void ldsm4(uint32_t* r, uint32_t a) {
    asm volatile("ldmatrix.sync.aligned.m8n8.x4.shared.b16 {%0,%1,%2,%3}, [%4];"
        : "=r"(r[0]), "=r"(r[1]), "=r"(r[2]), "=r"(r[3]) : "r"(a));
}
__device__ __forceinline__ void ldsm4t(uint32_t* r, uint32_t a) {
    asm volatile("ldmatrix.sync.aligned.m8n8.x4.trans.shared.b16 {%0,%1,%2,%3}, [%4];"
        : "=r"(r[0]), "=r"(r[1]), "=r"(r[2]), "=r"(r[3]) : "r"(a));
}
__device__ __forceinline__ void ldsm2(uint32_t* r, uint32_t a) {
    asm volatile("ldmatrix.sync.aligned.m8n8.x2.shared.b16 {%0,%1}, [%2];"
        : "=r"(r[0]), "=r"(r[1]) : "r"(a));
}
__device__ __forceinline__ void ldsm2t(uint32_t* r, uint32_t a) {
    asm volatile("ldmatrix.sync.aligned.m8n8.x2.trans.shared.b16 {%0,%1}, [%2];"
        : "=r"(r[0]), "=r"(r[1]) : "r"(a));
}
__device__ __forceinline__ void mma16816(float* d, const uint32_t* a, const uint32_t* b) {
    asm volatile("mma.sync.aligned.m16n8k16.row.col.f32.bf16.bf16.f32 "
        "{%0,%1,%2,%3}, {%4,%5,%6,%7}, {%8,%9}, {%0,%1,%2,%3};"
        : "+f"(d[0]), "+f"(d[1]), "+f"(d[2]), "+f"(d[3])
        : "r"(a[0]), "r"(a[1]), "r"(a[2]), "r"(a[3]), "r"(b[0]), "r"(b[1]));
}
__device__ __forceinline__ void split2(float a, float b, uint32_t& hi, uint32_t& lo) {
    __nv_bfloat162 h = __float22bfloat162_rn(make_float2(a, b));
    float2 hf = __bfloat1622float2(h);
    __nv_bfloat162 l = __float22bfloat162_rn(make_float2(a - hf.x, b - hf.y));
    hi = *(uint32_t*)&h; lo = *(uint32_t*)&l;
}

// ---------------------------------------------------------------------------
// convert kernels: fp32 -> bf16 hi/lo
// ---------------------------------------------------------------------------
__global__ __launch_bounds__(256) void conv_x_kernel(const float* __restrict__ x)
{
    size_t i = ((size_t)blockIdx.x*256 + threadIdx.x)*4;
    float4 v = *(const float4*)(x + i);
    uint32_t h0, l0, h1, l1;
    split2(v.x, v.y, h0, l0);
    split2(v.z, v.w, h1, l1);
    *(uint2*)(g_xh + i) = make_uint2(h0, h1);
    *(uint2*)(g_xl + i) = make_uint2(l0, l1);
}
__global__ __launch_bounds__(256) void conv_w_kernel(
    const float* __restrict__ Wk, const float* __restrict__ Wq, const float* __restrict__ Wv)
{
    const int w = blockIdx.y;
    const float* W = (w == 0) ? Wq : (w == 1) ? Wk : Wv;
    size_t base = (size_t)w*EMBED*HEAD;
    size_t i = ((size_t)blockIdx.x*256 + threadIdx.x)*4;
    float4 v = *(const float4*)(W + i);
    uint32_t h0, l0, h1, l1;
    split2(v.x, v.y, h0, l0);
    split2(v.z, v.w, h1, l1);
    *(uint2*)(g_wh + base + i) = make_uint2(h0, h1);
    *(uint2*)(g_wl + base + i) = make_uint2(l0, l1);
}

// ---------------------------------------------------------------------------
// zero / normalize
// ---------------------------------------------------------------------------
__global__ __launch_bounds__(256) void zero_kernel(float* __restrict__ out)
{
    int bid = blockIdx.x;
    if (bid < 2048) {
        size_t i = ((size_t)bid*256 + threadIdx.x)*4;
        *(float4*)(out + i) = make_float4(0.f, 0.f, 0.f, 0.f);
    } else {
        size_t i = ((size_t)(bid - 2048)*256 + threadIdx.x)*4;
        *(float4*)(g_l + i) = make_float4(0.f, 0.f, 0.f, 0.f);
    }
}
__global__ __launch_bounds__(256) void norm_kernel(float* __restrict__ out)
{
    size_t i4 = (size_t)blockIdx.x*256 + threadIdx.x;
    int row = (int)(i4 >> 5);
    float inv = 1.f / g_l[row];
    float4 v = *(float4*)(out + i4*4);
    v.x *= inv; v.y *= inv; v.z *= inv; v.w *= inv;
    *(float4*)(out + i4*4) = v;
}

// ---------------------------------------------------------------------------
// Projection GEMM on HMMA: 256 threads, 8 warps. Warp tile 32 rows x 64 cols
// (4 row-groups x 2 col-halves): B duplication 8->4, smem reads/chunk 320->192KB.
// smem/stage: XH 16K | XL 16K | WH 16K | WL 16K  (2 stages = 128KB)
// ---------------------------------------------------------------------------
#define PJ_STAGE 65536
#define PJ_SMEM  (2*PJ_STAGE)

__global__ __launch_bounds__(256, 1) void proj_kernel()
{
    extern __shared__ char sm[];
    const uint32_t smb = smem_u32(sm);
    const int tid = threadIdx.x, wid = tid >> 5, l = tid & 31;
    const int w = blockIdx.x;                 // weight index fastest -> L2 shares x
    const int row0 = blockIdx.y * 128;
    const int rg = wid & 3;                   // row group (32 rows)
    const int ch = wid >> 2;                  // col half  (64 cols)

    const __nv_bfloat16* xh = g_xh + (size_t)row0*EMBED;
    const __nv_bfloat16* xl = g_xl + (size_t)row0*EMBED;
    const __nv_bfloat16* wh = g_wh + (size_t)w*EMBED*HEAD;
    const __nv_bfloat16* wl = g_wl + (size_t)w*EMBED*HEAD;

    auto load_stage = [&](int s, int k0) {
        uint32_t sb = smb + s*PJ_STAGE;
        #pragma unroll
        for (int i = 0; i < 4; i++) {               // x tiles [128][64]
            int f = i*256 + tid;
            int r = f >> 3, c = f & 7;
            uint32_t d = sb + sidx(r, c*16, 128);
            cpa(d,         xh + (size_t)r*EMBED + k0 + c*8);
            cpa(d + 16384, xl + (size_t)r*EMBED + k0 + c*8);
        }
        #pragma unroll
        for (int i = 0; i < 4; i++) {               // W tiles [64][128]
            int f = i*256 + tid;
            int r = f >> 4, c = f & 15;
            uint32_t d = sb + 32768 + sidx(r, c*16, 256);
            cpa(d,         wh + (size_t)(k0 + r)*HEAD + c*8);
            cpa(d + 16384, wl + (size_t)(k0 + r)*HEAD + c*8);
        }
        CP_COMMIT();
    };

    float acc[2][8][4];
    #pragma unroll
    for (int m = 0; m < 2; m++)
        #pragma unroll
        for (int n = 0; n < 8; n++)
            #pragma unroll
            for (int j = 0; j < 4; j++) acc[m][n][j] = 0.f;

    load_stage(0, 0);

    for (int chk = 0; chk < 16; chk++) {
        int cur = chk & 1;
        if (chk + 1 < 16) { load_stage(cur ^ 1, (chk + 1)*64); CP_WAIT1(); }
        else              { CP_WAIT0(); }
        __syncthreads();

        uint32_t sb = smb + cur*PJ_STAGE;
        #pragma unroll
        for (int ks = 0; ks < 4; ks++) {
            uint32_t ah[2][4], al[2][4];
            #pragma unroll
            for (int m = 0; m < 2; m++) {
                uint32_t aoff = sidx(rg*32 + m*16 + (l & 15), ks*32 + ((l >> 4) << 4), 128);
                ldsm4(ah[m], sb + aoff);
                ldsm4(al[m], sb + 16384 + aoff);
            }
            #pragma unroll
            for (int np = 0; np < 4; np++) {
                uint32_t bh[4], bl[4];
                uint32_t boff = sidx(ks*16 + (l & 15),
                                     ch*128 + np*32 + ((l >> 4) & 1)*16, 256);
                ldsm4t(bh, sb + 32768 + boff);
                ldsm4t(bl, sb + 49152 + boff);
                #pragma unroll
                for (int m = 0; m < 2; m++) {
                    mma16816(acc[m][np*2],   ah[m], bh);
                    mma16816(acc[m][np*2],   ah[m], bl);
                    mma16816(acc[m][np*2],   al[m], bh);
                    mma16816(acc[m][np*2+1], ah[m], bh + 2);
                    mma16816(acc[m][np*2+1], ah[m], bl + 2);
                    mma16816(acc[m][np*2+1], al[m], bh + 2);
                }
            }
        }
        __syncthreads();
    }

    __nv_bfloat16* dh = (w == 0) ? g_qh : (w == 1) ? g_kh : g_vh;
    __nv_bfloat16* dl = (w == 0) ? g_ql : (w == 1) ? g_kl : g_vl;
    #pragma unroll
    for (int m = 0; m < 2; m++) {
        const int g0 = row0 + rg*32 + m*16 + (l >> 2);
        const int cb = ch*64 + (l & 3)*2;
        #pragma unroll
        for (int nt = 0; nt < 8; nt++) {
            uint32_t h, lo;
            split2(acc[m][nt][0], acc[m][nt][1], h, lo);
            *(uint32_t*)(dh + (size_t)g0*HEAD + cb + nt*8) = h;
            *(uint32_t*)(dl + (size_t)g0*HEAD + cb + nt*8) = lo;
            split2(acc[m][nt][2], acc[m][nt][3], h, lo);
            *(uint32_t*)(dh + (size_t)(g0 + 8)*HEAD + cb + nt*8) = h;
            *(uint32_t*)(dl + (size_t)(g0 + 8)*HEAD + cb + nt*8) = lo;
        }
    }
}

// ---------------------------------------------------------------------------
// Flash attention (exact R4 version, the 309us config): 8 warps, 64 queries,
// keys split across warp halves, split-KV chunks of 32 k-tiles.
// smem: QH 16K | QL 16K | 2 x stage{KH,KL,VH,VL each 16K} = 160KB
// ---------------------------------------------------------------------------
#define AT_KV0   32768
#define AT_STAGE 65536
#define AT_SMEM  (AT_KV0 + 2*AT_STAGE)
#define CHUNK    32   // k-tiles per CTA

__global__ __launch_bounds__(256, 1) void attn_kernel(float* __restrict__ out)
{
    const int qt = 63 - blockIdx.x;            // heavy q-tiles first
    const int c  = blockIdx.y;
    const int t0 = c*CHUNK;
    const int t1 = min(t0 + CHUNK, qt + 1);
    if (t0 >= t1) return;

    extern __shared__ char sm[];
    const uint32_t smb = smem_u32(sm);
    const int tid = threadIdx.x, wid = tid >> 5, l = tid & 31;
    const int b   = blockIdx.z;
    const int q0  = qt*64;
    const int wq  = (wid & 3)*16;              // query sub-tile
    const int kh  = wid >> 2;                  // key half (0/1)
    const bool single = (c == 0) && (qt + 1 <= CHUNK);

    // Q tiles (persistent); committed with first KV stage
    {
        const __nv_bfloat16* qh = g_qh + ((size_t)b*SEQ + q0)*HEAD;
        const __nv_bfloat16* ql = g_ql + ((size_t)b*SEQ + q0)*HEAD;
        #pragma unroll
        for (int i = 0; i < 4; i++) {
            int f = i*256 + tid;
            int r = f >> 4, cc = f & 15;
            uint32_t d = smb + sidx(r, cc*16, 256);
            cpa(d,         qh + (size_t)r*HEAD + cc*8);
            cpa(d + 16384, ql + (size_t)r*HEAD + cc*8);
        }
    }

    auto load_kv = [&](int s, int t) {
        uint32_t sb = smb + AT_KV0 + s*AT_STAGE;
        const size_t base = ((size_t)b*SEQ + t*64)*HEAD;
        #pragma unroll
        for (int i = 0; i < 4; i++) {
            int f = i*256 + tid;
            int r = f >> 4, cc = f & 15;
            uint32_t d = sb + sidx(r, cc*16, 256);
            const size_t g = base + (size_t)r*HEAD + cc*8;
            cpa(d,         g_kh + g);
            cpa(d + 16384, g_kl + g);
            cpa(d + 32768, g_vh + g);
            cpa(d + 49152, g_vl + g);
        }
        CP_COMMIT();
    };

    float o[16][4];
    #pragma unroll
    for (int n = 0; n < 16; n++)
        #pragma unroll
        for (int j = 0; j < 4; j++) o[n][j] = 0.f;
    float lsum0 = 0.f, lsum1 = 0.f;

    load_kv(0, t0);

    for (int t = t0; t < t1; t++) {
        int cur = (t - t0) & 1;
        if (t + 1 < t1) { load_kv(cur ^ 1, t + 1); CP_WAIT1(); }
        else            { CP_WAIT0(); }
        __syncthreads();

        uint32_t sb = smb + AT_KV0 + cur*AT_STAGE;

        // ---- scores S[16q x 32k] for this warp's key half ----
        float s[4][4];
        #pragma unroll
        for (int n = 0; n < 4; n++)
            #pragma unroll
            for (int j = 0; j < 4; j++) s[n][j] = 0.f;

        #pragma unroll
        for (int ks = 0; ks < 8; ks++) {
            uint32_t ah[4], al[4];
            uint32_t aoff = sidx(wq + (l & 15), ks*32 + ((l >> 4) << 4), 256);
            ldsm4(ah, smb + aoff);
            ldsm4(al, smb + 16384 + aoff);
            #pragma unroll
            for (int nt = 0; nt < 4; nt++) {
                uint32_t bh[2], bl2[2];
                uint32_t boff = sidx(kh*32 + nt*8 + (l & 7), ks*32 + ((l >> 3) & 1)*16, 256);
                ldsm2(bh,  sb + boff);
                ldsm2(bl2, sb + 16384 + boff);
                mma16816(s[nt], ah, bh);
                mma16816(s[nt], ah, bl2);
                mma16816(s[nt], al, bh);
            }
        }

        // ---- p = exp(s*scale), causal mask on diagonal tile ----
        uint32_t Ph[4][2], Pl[4][2];
        const bool diag = (t == qt);
        const int lq = q0 + wq + (l >> 2);
        #pragma unroll
        for (int nt = 0; nt < 4; nt++) {
            int kc = t*64 + kh*32 + nt*8 + (l & 3)*2;
            float p00 = __expf(s[nt][0]*SCALE);
            float p01 = __expf(s[nt][1]*SCALE);
            float p10 = __expf(s[nt][2]*SCALE);
            float p11 = __expf(s[nt][3]*SCALE);
            if (diag) {
                if (kc     > lq)     p00 = 0.f;
                if (kc + 1 > lq)     p01 = 0.f;
                if (kc     > lq + 8) p10 = 0.f;
                if (kc + 1 > lq + 8) p11 = 0.f;
            }
            lsum0 += p00 + p01;
            lsum1 += p10 + p11;
            split2(p00, p01, Ph[nt][0], Pl[nt][0]);
            split2(p10, p11, Ph[nt][1], Pl[nt][1]);
        }

        // ---- O += P * V over this warp's 32 keys ----
        #pragma unroll
        for (int ks = 0; ks < 2; ks++) {
            uint32_t ahh[4] = {Ph[2*ks][0], Ph[2*ks][1], Ph[2*ks+1][0], Ph[2*ks+1][1]};
            uint32_t all[4] = {Pl[2*ks][0], Pl[2*ks][1], Pl[2*ks+1][0], Pl[2*ks+1][1]};
            #pragma unroll
            for (int nt = 0; nt < 16; nt++) {
                uint32_t bh[2], bl2[2];
                uint32_t boff = sidx(kh*32 + ks*16 + (l & 15), nt*16, 256);
                ldsm2t(bh,  sb + 32768 + boff);
                ldsm2t(bl2, sb + 49152 + boff);
                mma16816(o[nt], ahh, bh);
                mma16816(o[nt], ahh, bl2);
                mma16816(o[nt], all, bh);
            }
        }
        __syncthreads();
    }

    // ---- cross-half reduction via smem (warps w and w+4 share queries) ----
    if (wid >= 4) {
        float* red = (float*)(sm + AT_KV0) + ((size_t)((wid - 4)*32 + l))*64;
        #pragma unroll
        for (int nt = 0; nt < 16; nt++)
            *(float4*)(red + nt*4) = make_float4(o[nt][0], o[nt][1], o[nt][2], o[nt][3]);
        float* lred = (float*)(sm + AT_KV0 + 32768) + ((wid - 4)*32 + l)*2;
        lred[0] = lsum0; lred[1] = lsum1;
    }
    __syncthreads();
    if (wid < 4) {
        float* red = (float*)(sm + AT_KV0) + ((size_t)(wid*32 + l))*64;
        #pragma unroll
        for (int nt = 0; nt < 16; nt++) {
            float4 r = *(float4*)(red + nt*4);
            o[nt][0] += r.x; o[nt][1] += r.y; o[nt][2] += r.z; o[nt][3] += r.w;
        }
        float* lred = (float*)(sm + AT_KV0 + 32768) + (wid*32 + l)*2;
        lsum0 += lred[0]; lsum1 += lred[1];

        lsum0 += __shfl_xor_sync(0xffffffffu, lsum0, 1);
        lsum0 += __shfl_xor_sync(0xffffffffu, lsum0, 2);
        lsum1 += __shfl_xor_sync(0xffffffffu, lsum1, 1);
        lsum1 += __shfl_xor_sync(0xffffffffu, lsum1, 2);

        const int row0g = q0 + wq + (l >> 2);
        const int cb = (l & 3)*2;
        float* og = out + ((size_t)b*SEQ + row0g)*HEAD;

        if (single) {
            #pragma unroll
            for (int nt = 0; nt < 16; nt++) {
                *(float2*)(og + nt*8 + cb) = make_float2(o[nt][0], o[nt][1]);
                *(float2*)(og + (size_t)8*HEAD + nt*8 + cb) = make_float2(o[nt][2], o[nt][3]);
            }
            if ((l & 3) == 0) {
                g_l[b*SEQ + row0g]     = lsum0;
                g_l[b*SEQ + row0g + 8] = lsum1;
            }
        } else {
            #pragma unroll
            for (int nt = 0; nt < 16; nt++) {
                atomicAdd(og + nt*8 + cb,     o[nt][0]);
                atomicAdd(og + nt*8 + cb + 1, o[nt][1]);
                atomicAdd(og + (size_t)8*HEAD + nt*8 + cb,     o[nt][2]);
                atomicAdd(og + (size_t)8*HEAD + nt*8 + cb + 1, o[nt][3]);
            }
            if ((l & 3) == 0) {
                atomicAdd(g_l + b*SEQ + row0g,     lsum0);
                atomicAdd(g_l + b*SEQ + row0g + 8, lsum1);
            }
        }
    }
}

// ---------------------------------------------------------------------------
extern "C" void kernel_launch(void* const* d_in, const int* in_sizes, int n_in,
                              void* d_out, int out_size)
{
    const float* x  = (const float*)d_in[0];
    const float* Wk = (const float*)d_in[1];
    const float* Wq = (const float*)d_in[2];
    const float* Wv = (const float*)d_in[3];
    float* out = (float*)d_out;

    cudaFuncSetAttribute(proj_kernel, cudaFuncAttributeMaxDynamicSharedMemorySize, PJ_SMEM);
    cudaFuncSetAttribute(attn_kernel, cudaFuncAttributeMaxDynamicSharedMemorySize, AT_SMEM);

    zero_kernel<<<2064, 256>>>(out);
    conv_x_kernel<<<BS*EMBED/1024, 256>>>(x);
    conv_w_kernel<<<dim3(EMBED*HEAD/1024, 3), 256>>>(Wk, Wq, Wv);
    proj_kernel<<<dim3(3, BS/128), 256, PJ_SMEM>>>();
    attn_kernel<<<dim3(64, (SEQ/64 + CHUNK - 1)/CHUNK, BATCH), 256, AT_SMEM>>>(out);
    norm_kernel<<<BS*HEAD/1024, 256>>>(out);
}

// round 7
// speedup vs baseline: 1.1686x; 1.1529x over previous
#include <cuda_runtime.h>
#include <cuda_bf16.h>
#include <cstdint>

#define EMBED 1024
#define HEAD  128
#define BATCH 4
#define SEQ   4096
#define BS    (BATCH*SEQ)
#define SCALE 0.03125f   // 1/sqrt(1024)

// ---------------------------------------------------------------------------
// Global scratch. Q,K: single bf16 (score path is error-tolerant).
// V: hi/lo split (output path needs precision). x,W: hi/lo for V projection.
// ---------------------------------------------------------------------------
__device__ __align__(256) __nv_bfloat16 g_xh[BS*EMBED], g_xl[BS*EMBED];
__device__ __align__(256) __nv_bfloat16 g_wh[3*EMBED*HEAD], g_wl[3*EMBED*HEAD];
__device__ __align__(256) __nv_bfloat16 g_qh[BS*HEAD];
__device__ __align__(256) __nv_bfloat16 g_kh[BS*HEAD];
__device__ __align__(256) __nv_bfloat16 g_vh[BS*HEAD], g_vl[BS*HEAD];
__device__ __align__(256) float g_l[BS];

// ---------------------------------------------------------------------------
// helpers
// ---------------------------------------------------------------------------
__device__ __forceinline__ uint32_t smem_u32(const void* p) {
    uint32_t a;
    asm("{ .reg .u64 t; cvta.to.shared.u64 t, %1; cvt.u32.u64 %0, t; }" : "=r"(a) : "l"(p));
    return a;
}
__device__ __forceinline__ uint32_t sidx(int row, int cb, int rb) {
    return (uint32_t)(row*rb + ((((cb >> 4) ^ (row & 7)) << 4) | (cb & 15)));
}
__device__ __forceinline__ void cpa(uint32_t d, const void* s) {
    asm volatile("cp.async.cg.shared.global [%0], [%1], 16;" :: "r"(d), "l"(s));
}
#define CP_COMMIT() asm volatile("cp.async.commit_group;" ::: "memory")
#define CP_WAIT0()  asm volatile("cp.async.wait_group 0;" ::: "memory")
#define CP_WAIT1()  asm volatile("cp.async.wait_group 1;" ::: "memory")

__device__ __forceinline__ void ldsm4(uint32_t* r, uint32_t a) {
    asm volatile("ldmatrix.sync.aligned.m8n8.x4.shared.b16 {%0,%1,%2,%3}, [%4];"
        : "=r"(r[0]), "=r"(r[1]), "=r"(r[2]), "=r"(r[3]) : "r"(a));
}
__device__ __forceinline__ void ldsm4t(uint32_t* r, uint32_t a) {
    asm volatile("ldmatrix.sync.aligned.m8n8.x4.trans.shared.b16 {%0,%1,%2,%3}, [%4];"
        : "=r"(r[0]), "=r"(r[1]), "=r"(r[2]), "=r"(r[3]) : "r"(a));
}
__device__ __forceinline__ void ldsm2(uint32_t* r, uint32_t a) {
    asm volatile("ldmatrix.sync.aligned.m8n8.x2.shared.b16 {%0,%1}, [%2];"
        : "=r"(r[0]), "=r"(r[1]) : "r"(a));
}
__device__ __forceinline__ void ldsm2t(uint32_t* r, uint32_t a) {
    asm volatile("ldmatrix.sync.aligned.m8n8.x2.trans.shared.b16 {%0,%1}, [%2];"
        : "=r"(r[0]), "=r"(r[1]) : "r"(a));
}
__device__ __forceinline__ void mma16816(float* d, const uint32_t* a, const uint32_t* b) {
    asm volatile("mma.sync.aligned.m16n8k16.row.col.f32.bf16.bf16.f32 "
        "{%0,%1,%2,%3}, {%4,%5,%6,%7}, {%8,%9}, {%0,%1,%2,%3};"
        : "+f"(d[0]), "+f"(d[1]), "+f"(d[2]), "+f"(d[3])
        : "r"(a[0]), "r"(a[1]), "r"(a[2]), "r"(a[3]), "r"(b[0]), "r"(b[1]));
}
__device__ __forceinline__ void split2(float a, float b, uint32_t& hi, uint32_t& lo) {
    __nv_bfloat162 h = __float22bfloat162_rn(make_float2(a, b));
    float2 hf = __bfloat1622float2(h);
    __nv_bfloat162 l = __float22bfloat162_rn(make_float2(a - hf.x, b - hf.y));
    hi = *(uint32_t*)&h; lo = *(uint32_t*)&l;
}
__device__ __forceinline__ uint32_t pack2(float a, float b) {
    __nv_bfloat162 h = __float22bfloat162_rn(make_float2(a, b));
    return *(uint32_t*)&h;
}

// ---------------------------------------------------------------------------
// convert kernels: fp32 -> bf16 hi/lo
// ---------------------------------------------------------------------------
__global__ __launch_bounds__(256) void conv_x_kernel(const float* __restrict__ x)
{
    size_t i = ((size_t)blockIdx.x*256 + threadIdx.x)*4;
    float4 v = *(const float4*)(x + i);
    uint32_t h0, l0, h1, l1;
    split2(v.x, v.y, h0, l0);
    split2(v.z, v.w, h1, l1);
    *(uint2*)(g_xh + i) = make_uint2(h0, h1);
    *(uint2*)(g_xl + i) = make_uint2(l0, l1);
}
__global__ __launch_bounds__(256) void conv_w_kernel(
    const float* __restrict__ Wk, const float* __restrict__ Wq, const float* __restrict__ Wv)
{
    const int w = blockIdx.y;
    const float* W = (w == 0) ? Wq : (w == 1) ? Wk : Wv;
    size_t base = (size_t)w*EMBED*HEAD;
    size_t i = ((size_t)blockIdx.x*256 + threadIdx.x)*4;
    float4 v = *(const float4*)(W + i);
    uint32_t h0, l0, h1, l1;
    split2(v.x, v.y, h0, l0);
    split2(v.z, v.w, h1, l1);
    *(uint2*)(g_wh + base + i) = make_uint2(h0, h1);
    *(uint2*)(g_wl + base + i) = make_uint2(l0, l1);
}

// ---------------------------------------------------------------------------
// zero / normalize
// ---------------------------------------------------------------------------
__global__ __launch_bounds__(256) void zero_kernel(float* __restrict__ out)
{
    int bid = blockIdx.x;
    if (bid < 2048) {
        size_t i = ((size_t)bid*256 + threadIdx.x)*4;
        *(float4*)(out + i) = make_float4(0.f, 0.f, 0.f, 0.f);
    } else {
        size_t i = ((size_t)(bid - 2048)*256 + threadIdx.x)*4;
        *(float4*)(g_l + i) = make_float4(0.f, 0.f, 0.f, 0.f);
    }
}
__global__ __launch_bounds__(256) void norm_kernel(float* __restrict__ out)
{
    size_t i4 = (size_t)blockIdx.x*256 + threadIdx.x;
    int row = (int)(i4 >> 5);
    float inv = 1.f / g_l[row];
    float4 v = *(float4*)(out + i4*4);
    v.x *= inv; v.y *= inv; v.z *= inv; v.w *= inv;
    *(float4*)(out + i4*4) = v;
}

// ---------------------------------------------------------------------------
// Projection GEMM on HMMA. Q,K: single-pass bf16 (xh*Wh). V: 3-pass split.
// 256 threads, warp tile 32 rows x 64 cols.
// smem/stage: XH 16K | XL 16K | WH 16K | WL 16K  (2 stages = 128KB)
// ---------------------------------------------------------------------------
#define PJ_STAGE 65536
#define PJ_SMEM  (2*PJ_STAGE)

__global__ __launch_bounds__(256, 1) void proj_kernel()
{
    extern __shared__ char sm[];
    const uint32_t smb = smem_u32(sm);
    const int tid = threadIdx.x, wid = tid >> 5, l = tid & 31;
    const int w = blockIdx.x;
    const bool three = (w == 2);               // V needs 3 passes
    const int row0 = blockIdx.y * 128;
    const int rg = wid & 3;
    const int ch = wid >> 2;

    const __nv_bfloat16* xh = g_xh + (size_t)row0*EMBED;
    const __nv_bfloat16* xl = g_xl + (size_t)row0*EMBED;
    const __nv_bfloat16* wh = g_wh + (size_t)w*EMBED*HEAD;
    const __nv_bfloat16* wl = g_wl + (size_t)w*EMBED*HEAD;

    auto load_stage = [&](int s, int k0) {
        uint32_t sb = smb + s*PJ_STAGE;
        #pragma unroll
        for (int i = 0; i < 4; i++) {
            int f = i*256 + tid;
            int r = f >> 3, c = f & 7;
            uint32_t d = sb + sidx(r, c*16, 128);
            cpa(d, xh + (size_t)r*EMBED + k0 + c*8);
            if (three) cpa(d + 16384, xl + (size_t)r*EMBED + k0 + c*8);
        }
        #pragma unroll
        for (int i = 0; i < 4; i++) {
            int f = i*256 + tid;
            int r = f >> 4, c = f & 15;
            uint32_t d = sb + 32768 + sidx(r, c*16, 256);
            cpa(d, wh + (size_t)(k0 + r)*HEAD + c*8);
            if (three) cpa(d + 16384, wl + (size_t)(k0 + r)*HEAD + c*8);
        }
        CP_COMMIT();
    };

    float acc[2][8][4];
    #pragma unroll
    for (int m = 0; m < 2; m++)
        #pragma unroll
        for (int n = 0; n < 8; n++)
            #pragma unroll
            for (int j = 0; j < 4; j++) acc[m][n][j] = 0.f;

    load_stage(0, 0);

    for (int chk = 0; chk < 16; chk++) {
        int cur = chk & 1;
        if (chk + 1 < 16) { load_stage(cur ^ 1, (chk + 1)*64); CP_WAIT1(); }
        else              { CP_WAIT0(); }
        __syncthreads();

        uint32_t sb = smb + cur*PJ_STAGE;
        #pragma unroll
        for (int ks = 0; ks < 4; ks++) {
            uint32_t ah[2][4], al[2][4];
            #pragma unroll
            for (int m = 0; m < 2; m++) {
                uint32_t aoff = sidx(rg*32 + m*16 + (l & 15), ks*32 + ((l >> 4) << 4), 128);
                ldsm4(ah[m], sb + aoff);
                if (three) ldsm4(al[m], sb + 16384 + aoff);
            }
            #pragma unroll
            for (int np = 0; np < 4; np++) {
                uint32_t bh[4], bl[4];
                uint32_t boff = sidx(ks*16 + (l & 15),
                                     ch*128 + np*32 + ((l >> 4) & 1)*16, 256);
                ldsm4t(bh, sb + 32768 + boff);
                if (three) ldsm4t(bl, sb + 49152 + boff);
                #pragma unroll
                for (int m = 0; m < 2; m++) {
                    mma16816(acc[m][np*2],   ah[m], bh);
                    mma16816(acc[m][np*2+1], ah[m], bh + 2);
                    if (three) {
                        mma16816(acc[m][np*2],   ah[m], bl);
                        mma16816(acc[m][np*2],   al[m], bh);
                        mma16816(acc[m][np*2+1], ah[m], bl + 2);
                        mma16816(acc[m][np*2+1], al[m], bh + 2);
                    }
                }
            }
        }
        __syncthreads();
    }

    if (!three) {
        __nv_bfloat16* dh = (w == 0) ? g_qh : g_kh;
        #pragma unroll
        for (int m = 0; m < 2; m++) {
            const int g0 = row0 + rg*32 + m*16 + (l >> 2);
            const int cb = ch*64 + (l & 3)*2;
            #pragma unroll
            for (int nt = 0; nt < 8; nt++) {
                *(uint32_t*)(dh + (size_t)g0*HEAD + cb + nt*8) =
                    pack2(acc[m][nt][0], acc[m][nt][1]);
                *(uint32_t*)(dh + (size_t)(g0 + 8)*HEAD + cb + nt*8) =
                    pack2(acc[m][nt][2], acc[m][nt][3]);
            }
        }
    } else {
        #pragma unroll
        for (int m = 0; m < 2; m++) {
            const int g0 = row0 + rg*32 + m*16 + (l >> 2);
            const int cb = ch*64 + (l & 3)*2;
            #pragma unroll
            for (int nt = 0; nt < 8; nt++) {
                uint32_t h, lo;
                split2(acc[m][nt][0], acc[m][nt][1], h, lo);
                *(uint32_t*)(g_vh + (size_t)g0*HEAD + cb + nt*8) = h;
                *(uint32_t*)(g_vl + (size_t)g0*HEAD + cb + nt*8) = lo;
                split2(acc[m][nt][2], acc[m][nt][3], h, lo);
                *(uint32_t*)(g_vh + (size_t)(g0 + 8)*HEAD + cb + nt*8) = h;
                *(uint32_t*)(g_vl + (size_t)(g0 + 8)*HEAD + cb + nt*8) = lo;
            }
        }
    }
}

// ---------------------------------------------------------------------------
// Flash attention: single-pass scores (qh*kh), 3-pass PV (P split, V hi/lo).
// 8 warps, 64 queries, keys split across warp halves, split-KV CHUNK=32.
// smem: QH 16K | 2 x stage{KH,VH,VL each 16K} = 112KB
// ---------------------------------------------------------------------------
#define AT_KV0   16384
#define AT_STAGE 49152
#define AT_SMEM  (AT_KV0 + 2*AT_STAGE)
#define CHUNK    32

__global__ __launch_bounds__(256, 1) void attn_kernel(float* __restrict__ out)
{
    const int qt = 63 - blockIdx.x;
    const int c  = blockIdx.y;
    const int t0 = c*CHUNK;
    const int t1 = min(t0 + CHUNK, qt + 1);
    if (t0 >= t1) return;

    extern __shared__ char sm[];
    const uint32_t smb = smem_u32(sm);
    const int tid = threadIdx.x, wid = tid >> 5, l = tid & 31;
    const int b   = blockIdx.z;
    const int q0  = qt*64;
    const int wq  = (wid & 3)*16;
    const int kh  = wid >> 2;
    const bool single = (c == 0) && (qt + 1 <= CHUNK);

    // Q tile (qh only, persistent)
    {
        const __nv_bfloat16* qh = g_qh + ((size_t)b*SEQ + q0)*HEAD;
        #pragma unroll
        for (int i = 0; i < 4; i++) {
            int f = i*256 + tid;
            int r = f >> 4, cc = f & 15;
            cpa(smb + sidx(r, cc*16, 256), qh + (size_t)r*HEAD + cc*8);
        }
    }

    auto load_kv = [&](int s, int t) {
        uint32_t sb = smb + AT_KV0 + s*AT_STAGE;
        const size_t base = ((size_t)b*SEQ + t*64)*HEAD;
        #pragma unroll
        for (int i = 0; i < 4; i++) {
            int f = i*256 + tid;
            int r = f >> 4, cc = f & 15;
            uint32_t d = sb + sidx(r, cc*16, 256);
            const size_t g = base + (size_t)r*HEAD + cc*8;
            cpa(d,         g_kh + g);
            cpa(d + 16384, g_vh + g);
            cpa(d + 32768, g_vl + g);
        }
        CP_COMMIT();
    };

    float o[16][4];
    #pragma unroll
    for (int n = 0; n < 16; n++)
        #pragma unroll
        for (int j = 0; j < 4; j++) o[n][j] = 0.f;
    float lsum0 = 0.f, lsum1 = 0.f;

    load_kv(0, t0);

    for (int t = t0; t < t1; t++) {
        int cur = (t - t0) & 1;
        if (t + 1 < t1) { load_kv(cur ^ 1, t + 1); CP_WAIT1(); }
        else            { CP_WAIT0(); }
        __syncthreads();

        uint32_t sb = smb + AT_KV0 + cur*AT_STAGE;

        // ---- scores: single-pass qh*kh ----
        float s[4][4];
        #pragma unroll
        for (int n = 0; n < 4; n++)
            #pragma unroll
            for (int j = 0; j < 4; j++) s[n][j] = 0.f;

        #pragma unroll
        for (int ks = 0; ks < 8; ks++) {
            uint32_t ah[4];
            uint32_t aoff = sidx(wq + (l & 15), ks*32 + ((l >> 4) << 4), 256);
            ldsm4(ah, smb + aoff);
            #pragma unroll
            for (int nt = 0; nt < 4; nt++) {
                uint32_t bh[2];
                uint32_t boff = sidx(kh*32 + nt*8 + (l & 7), ks*32 + ((l >> 3) & 1)*16, 256);
                ldsm2(bh, sb + boff);
                mma16816(s[nt], ah, bh);
            }
        }

        // ---- p = exp(s*scale), causal mask, split to bf16 hi/lo ----
        uint32_t Ph[4][2], Pl[4][2];
        const bool diag = (t == qt);
        const int lq = q0 + wq + (l >> 2);
        #pragma unroll
        for (int nt = 0; nt < 4; nt++) {
            int kc = t*64 + kh*32 + nt*8 + (l & 3)*2;
            float p00 = __expf(s[nt][0]*SCALE);
            float p01 = __expf(s[nt][1]*SCALE);
            float p10 = __expf(s[nt][2]*SCALE);
            float p11 = __expf(s[nt][3]*SCALE);
            if (diag) {
                if (kc     > lq)     p00 = 0.f;
                if (kc + 1 > lq)     p01 = 0.f;
                if (kc     > lq + 8) p10 = 0.f;
                if (kc + 1 > lq + 8) p11 = 0.f;
            }
            lsum0 += p00 + p01;
            lsum1 += p10 + p11;
            split2(p00, p01, Ph[nt][0], Pl[nt][0]);
            split2(p10, p11, Ph[nt][1], Pl[nt][1]);
        }

        // ---- O += P*Vh + P*Vl + Pl*Vh (3 passes) ----
        #pragma unroll
        for (int ks = 0; ks < 2; ks++) {
            uint32_t ahh[4] = {Ph[2*ks][0], Ph[2*ks][1], Ph[2*ks+1][0], Ph[2*ks+1][1]};
            uint32_t all[4] = {Pl[2*ks][0], Pl[2*ks][1], Pl[2*ks+1][0], Pl[2*ks+1][1]};
            #pragma unroll
            for (int nt = 0; nt < 16; nt++) {
                uint32_t bh[2], bl2[2];
                uint32_t boff = sidx(kh*32 + ks*16 + (l & 15), nt*16, 256);
                ldsm2t(bh,  sb + 16384 + boff);
                ldsm2t(bl2, sb + 32768 + boff);
                mma16816(o[nt], ahh, bh);
                mma16816(o[nt], ahh, bl2);
                mma16816(o[nt], all, bh);
            }
        }
        __syncthreads();
    }

    // ---- cross-half reduction via smem ----
    if (wid >= 4) {
        float* red = (float*)(sm + AT_KV0) + ((size_t)((wid - 4)*32 + l))*64;
        #pragma unroll
        for (int nt = 0; nt < 16; nt++)
            *(float4*)(red + nt*4) = make_float4(o[nt][0], o[nt][1], o[nt][2], o[nt][3]);
        float* lred = (float*)(sm + AT_KV0 + 32768) + ((wid - 4)*32 + l)*2;
        lred[0] = lsum0; lred[1] = lsum1;
    }
    __syncthreads();
    if (wid < 4) {
        float* red = (float*)(sm + AT_KV0) + ((size_t)(wid*32 + l))*64;
        #pragma unroll
        for (int nt = 0; nt < 16; nt++) {
            float4 r = *(float4*)(red + nt*4);
            o[nt][0] += r.x; o[nt][1] += r.y; o[nt][2] += r.z; o[nt][3] += r.w;
        }
        float* lred = (float*)(sm + AT_KV0 + 32768) + (wid*32 + l)*2;
        lsum0 += lred[0]; lsum1 += lred[1];

        lsum0 += __shfl_xor_sync(0xffffffffu, lsum0, 1);
        lsum0 += __shfl_xor_sync(0xffffffffu, lsum0, 2);
        lsum1 += __shfl_xor_sync(0xffffffffu, lsum1, 1);
        lsum1 += __shfl_xor_sync(0xffffffffu, lsum1, 2);

        const int row0g = q0 + wq + (l >> 2);
        const int cb = (l & 3)*2;
        float* og = out + ((size_t)b*SEQ + row0g)*HEAD;

        if (single) {
            #pragma unroll
            for (int nt = 0; nt < 16; nt++) {
                *(float2*)(og + nt*8 + cb) = make_float2(o[nt][0], o[nt][1]);
                *(float2*)(og + (size_t)8*HEAD + nt*8 + cb) = make_float2(o[nt][2], o[nt][3]);
            }
            if ((l & 3) == 0) {
                g_l[b*SEQ + row0g]     = lsum0;
                g_l[b*SEQ + row0g + 8] = lsum1;
            }
        } else {
            #pragma unroll
            for (int nt = 0; nt < 16; nt++) {
                atomicAdd(og + nt*8 + cb,     o[nt][0]);
                atomicAdd(og + nt*8 + cb + 1, o[nt][1]);
                atomicAdd(og + (size_t)8*HEAD + nt*8 + cb,     o[nt][2]);
                atomicAdd(og + (size_t)8*HEAD + nt*8 + cb + 1, o[nt][3]);
            }
            if ((l & 3) == 0) {
                atomicAdd(g_l + b*SEQ + row0g,     lsum0);
                atomicAdd(g_l + b*SEQ + row0g + 8, lsum1);
            }
        }
    }
}

// ---------------------------------------------------------------------------
extern "C" void kernel_launch(void* const* d_in, const int* in_sizes, int n_in,
                              void* d_out, int out_size)
{
    const float* x  = (const float*)d_in[0];
    const float* Wk = (const float*)d_in[1];
    const float* Wq = (const float*)d_in[2];
    const float* Wv = (const float*)d_in[3];
    float* out = (float*)d_out;

    cudaFuncSetAttribute(proj_kernel, cudaFuncAttributeMaxDynamicSharedMemorySize, PJ_SMEM);
    cudaFuncSetAttribute(attn_kernel, cudaFuncAttributeMaxDynamicSharedMemorySize, AT_SMEM);

    zero_kernel<<<2064, 256>>>(out);
    conv_x_kernel<<<BS*EMBED/1024, 256>>>(x);
    conv_w_kernel<<<dim3(EMBED*HEAD/1024, 3), 256>>>(Wk, Wq, Wv);
    proj_kernel<<<dim3(3, BS/128), 256, PJ_SMEM>>>();
    attn_kernel<<<dim3(64, (SEQ/64 + CHUNK - 1)/CHUNK, BATCH), 256, AT_SMEM>>>(out);
    norm_kernel<<<BS*HEAD/1024, 256>>>(out);
}

// round 8
// speedup vs baseline: 1.8792x; 1.6080x over previous
#include <cuda_runtime.h>
#include <cuda_fp16.h>
#include <cstdint>

#define EMBED 1024
#define HEAD  128
#define BATCH 4
#define SEQ   4096
#define BS    (BATCH*SEQ)
#define SCALE 0.03125f   // 1/sqrt(1024)

// ---------------------------------------------------------------------------
// Global scratch: everything single fp16 (11-bit mantissa covers 1e-3 budget)
// ---------------------------------------------------------------------------
__device__ __align__(256) __half g_x[BS*EMBED];
__device__ __align__(256) __half g_w[3*EMBED*HEAD];
__device__ __align__(256) __half g_q[BS*HEAD], g_k[BS*HEAD], g_v[BS*HEAD];
__device__ __align__(256) float g_l[BS];

// ---------------------------------------------------------------------------
// helpers
// ---------------------------------------------------------------------------
__device__ __forceinline__ uint32_t smem_u32(const void* p) {
    uint32_t a;
    asm("{ .reg .u64 t; cvta.to.shared.u64 t, %1; cvt.u32.u64 %0, t; }" : "=r"(a) : "l"(p));
    return a;
}
__device__ __forceinline__ uint32_t sidx(int row, int cb, int rb) {
    return (uint32_t)(row*rb + ((((cb >> 4) ^ (row & 7)) << 4) | (cb & 15)));
}
__device__ __forceinline__ void cpa(uint32_t d, const void* s) {
    asm volatile("cp.async.cg.shared.global [%0], [%1], 16;" :: "r"(d), "l"(s));
}
#define CP_COMMIT() asm volatile("cp.async.commit_group;" ::: "memory")
#define CP_WAIT0()  asm volatile("cp.async.wait_group 0;" ::: "memory")
#define CP_WAIT1()  asm volatile("cp.async.wait_group 1;" ::: "memory")
#define CP_WAIT2()  asm volatile("cp.async.wait_group 2;" ::: "memory")
#define CP_WAIT3()  asm volatile("cp.async.wait_group 3;" ::: "memory")
__device__ __forceinline__ void cp_wait_rem(int rem) {
    if (rem >= 3)      CP_WAIT3();
    else if (rem == 2) CP_WAIT2();
    else if (rem == 1) CP_WAIT1();
    else               CP_WAIT0();
}

__device__ __forceinline__ void ldsm4(uint32_t* r, uint32_t a) {
    asm volatile("ldmatrix.sync.aligned.m8n8.x4.shared.b16 {%0,%1,%2,%3}, [%4];"
        : "=r"(r[0]), "=r"(r[1]), "=r"(r[2]), "=r"(r[3]) : "r"(a));
}
__device__ __forceinline__ void ldsm4t(uint32_t* r, uint32_t a) {
    asm volatile("ldmatrix.sync.aligned.m8n8.x4.trans.shared.b16 {%0,%1,%2,%3}, [%4];"
        : "=r"(r[0]), "=r"(r[1]), "=r"(r[2]), "=r"(r[3]) : "r"(a));
}
__device__ __forceinline__ void mma16816(float* d, const uint32_t* a, const uint32_t* b) {
    asm volatile("mma.sync.aligned.m16n8k16.row.col.f32.f16.f16.f32 "
        "{%0,%1,%2,%3}, {%4,%5,%6,%7}, {%8,%9}, {%0,%1,%2,%3};"
        : "+f"(d[0]), "+f"(d[1]), "+f"(d[2]), "+f"(d[3])
        : "r"(a[0]), "r"(a[1]), "r"(a[2]), "r"(a[3]), "r"(b[0]), "r"(b[1]));
}
__device__ __forceinline__ uint32_t packh2(float a, float b) {
    __half2 h = __floats2half2_rn(a, b);
    return *(uint32_t*)&h;
}

// ---------------------------------------------------------------------------
// convert kernels: fp32 -> fp16
// ---------------------------------------------------------------------------
__global__ __launch_bounds__(256) void conv_x_kernel(const float* __restrict__ x)
{
    size_t i = ((size_t)blockIdx.x*256 + threadIdx.x)*4;
    float4 v = *(const float4*)(x + i);
    *(uint2*)(g_x + i) = make_uint2(packh2(v.x, v.y), packh2(v.z, v.w));
}
__global__ __launch_bounds__(256) void conv_w_kernel(
    const float* __restrict__ Wk, const float* __restrict__ Wq, const float* __restrict__ Wv)
{
    const int w = blockIdx.y;
    const float* W = (w == 0) ? Wq : (w == 1) ? Wk : Wv;
    size_t base = (size_t)w*EMBED*HEAD;
    size_t i = ((size_t)blockIdx.x*256 + threadIdx.x)*4;
    float4 v = *(const float4*)(W + i);
    *(uint2*)(g_w + base + i) = make_uint2(packh2(v.x, v.y), packh2(v.z, v.w));
}

// ---------------------------------------------------------------------------
// zero / normalize
// ---------------------------------------------------------------------------
__global__ __launch_bounds__(256) void zero_kernel(float* __restrict__ out)
{
    int bid = blockIdx.x;
    if (bid < 2048) {
        size_t i = ((size_t)bid*256 + threadIdx.x)*4;
        *(float4*)(out + i) = make_float4(0.f, 0.f, 0.f, 0.f);
    } else {
        size_t i = ((size_t)(bid - 2048)*256 + threadIdx.x)*4;
        *(float4*)(g_l + i) = make_float4(0.f, 0.f, 0.f, 0.f);
    }
}
__global__ __launch_bounds__(256) void norm_kernel(float* __restrict__ out)
{
    size_t i4 = (size_t)blockIdx.x*256 + threadIdx.x;
    int row = (int)(i4 >> 5);
    float inv = 1.f / g_l[row];
    float4 v = *(float4*)(out + i4*4);
    v.x *= inv; v.y *= inv; v.z *= inv; v.w *= inv;
    *(float4*)(out + i4*4) = v;
}

// ---------------------------------------------------------------------------
// Projection GEMM, fp16 single-pass, 4-stage cp.async ring.
// 256 threads, warp tile 32 rows x 64 cols.
// stage = X 16K | W 16K (32KB); 4 stages = 128KB.
// ---------------------------------------------------------------------------
#define PJ_STAGE 32768
#define PJ_SMEM  (4*PJ_STAGE)

__global__ __launch_bounds__(256, 1) void proj_kernel()
{
    extern __shared__ char sm[];
    const uint32_t smb = smem_u32(sm);
    const int tid = threadIdx.x, wid = tid >> 5, l = tid & 31;
    const int w = blockIdx.x;
    const int row0 = blockIdx.y * 128;
    const int rg = wid & 3;
    const int ch = wid >> 2;

    const __half* xg = g_x + (size_t)row0*EMBED;
    const __half* wg = g_w + (size_t)w*EMBED*HEAD;

    auto load_stage = [&](int s, int k0) {
        uint32_t sb = smb + s*PJ_STAGE;
        #pragma unroll
        for (int i = 0; i < 4; i++) {               // x tile [128][64]
            int f = i*256 + tid;
            int r = f >> 3, c = f & 7;
            cpa(sb + sidx(r, c*16, 128), xg + (size_t)r*EMBED + k0 + c*8);
        }
        #pragma unroll
        for (int i = 0; i < 4; i++) {               // W tile [64][128]
            int f = i*256 + tid;
            int r = f >> 4, c = f & 15;
            cpa(sb + 16384 + sidx(r, c*16, 256), wg + (size_t)(k0 + r)*HEAD + c*8);
        }
        CP_COMMIT();
    };

    float acc[2][8][4];
    #pragma unroll
    for (int m = 0; m < 2; m++)
        #pragma unroll
        for (int n = 0; n < 8; n++)
            #pragma unroll
            for (int j = 0; j < 4; j++) acc[m][n][j] = 0.f;

    load_stage(0, 0);
    load_stage(1, 64);
    load_stage(2, 128);

    for (int chk = 0; chk < 16; chk++) {
        if (chk + 3 < 16) load_stage((chk + 3) & 3, (chk + 3)*64);
        cp_wait_rem(15 - chk);
        __syncthreads();

        uint32_t sb = smb + (chk & 3)*PJ_STAGE;
        #pragma unroll
        for (int ks = 0; ks < 4; ks++) {
            uint32_t ah[2][4];
            #pragma unroll
            for (int m = 0; m < 2; m++) {
                uint32_t aoff = sidx(rg*32 + m*16 + (l & 15), ks*32 + ((l >> 4) << 4), 128);
                ldsm4(ah[m], sb + aoff);
            }
            #pragma unroll
            for (int np = 0; np < 4; np++) {
                uint32_t bh[4];
                uint32_t boff = sidx(ks*16 + (l & 15),
                                     ch*128 + np*32 + ((l >> 4) & 1)*16, 256);
                ldsm4t(bh, sb + 16384 + boff);
                #pragma unroll
                for (int m = 0; m < 2; m++) {
                    mma16816(acc[m][np*2],   ah[m], bh);
                    mma16816(acc[m][np*2+1], ah[m], bh + 2);
                }
            }
        }
        __syncthreads();
    }

    __half* dst = (w == 0) ? g_q : (w == 1) ? g_k : g_v;
    #pragma unroll
    for (int m = 0; m < 2; m++) {
        const int g0 = row0 + rg*32 + m*16 + (l >> 2);
        const int cb = ch*64 + (l & 3)*2;
        #pragma unroll
        for (int nt = 0; nt < 8; nt++) {
            *(uint32_t*)(dst + (size_t)g0*HEAD + cb + nt*8) =
                packh2(acc[m][nt][0], acc[m][nt][1]);
            *(uint32_t*)(dst + (size_t)(g0 + 8)*HEAD + cb + nt*8) =
                packh2(acc[m][nt][2], acc[m][nt][3]);
        }
    }
}

// ---------------------------------------------------------------------------
// Flash attention: fp16 single-pass scores AND PV, 4-stage KV ring.
// 8 warps, 64 queries, keys split across warp halves, split-KV CHUNK=32.
// smem: Q 16K | 4 x stage{K 16K, V 16K} = 144KB
// ---------------------------------------------------------------------------
#define AT_KV0   16384
#define AT_STAGE 32768
#define AT_SMEM  (AT_KV0 + 4*AT_STAGE)
#define CHUNK    32

__global__ __launch_bounds__(256, 1) void attn_kernel(float* __restrict__ out)
{
    const int qt = 63 - blockIdx.x;
    const int c  = blockIdx.y;
    const int t0 = c*CHUNK;
    const int t1 = min(t0 + CHUNK, qt + 1);
    if (t0 >= t1) return;

    extern __shared__ char sm[];
    const uint32_t smb = smem_u32(sm);
    const int tid = threadIdx.x, wid = tid >> 5, l = tid & 31;
    const int b   = blockIdx.z;
    const int q0  = qt*64;
    const int wq  = (wid & 3)*16;
    const int kh  = wid >> 2;
    const bool single = (c == 0) && (qt + 1 <= CHUNK);
    const int n = t1 - t0;

    // Q tile (persistent) — joins group 0 (first load_kv commit)
    {
        const __half* qg = g_q + ((size_t)b*SEQ + q0)*HEAD;
        #pragma unroll
        for (int i = 0; i < 4; i++) {
            int f = i*256 + tid;
            int r = f >> 4, cc = f & 15;
            cpa(smb + sidx(r, cc*16, 256), qg + (size_t)r*HEAD + cc*8);
        }
    }

    auto load_kv = [&](int s, int t) {
        uint32_t sb = smb + AT_KV0 + s*AT_STAGE;
        const size_t base = ((size_t)b*SEQ + t*64)*HEAD;
        #pragma unroll
        for (int i = 0; i < 4; i++) {
            int f = i*256 + tid;
            int r = f >> 4, cc = f & 15;
            uint32_t d = sb + sidx(r, cc*16, 256);
            const size_t g = base + (size_t)r*HEAD + cc*8;
            cpa(d,         g_k + g);
            cpa(d + 16384, g_v + g);
        }
        CP_COMMIT();
    };

    float o[16][4];
    #pragma unroll
    for (int nn = 0; nn < 16; nn++)
        #pragma unroll
        for (int j = 0; j < 4; j++) o[nn][j] = 0.f;
    float lsum0 = 0.f, lsum1 = 0.f;

    const int pf = (n < 3) ? n : 3;
    for (int i = 0; i < pf; i++) load_kv(i, t0 + i);

    for (int t = t0; t < t1; t++) {
        const int idx = t - t0;
        if (idx + 3 < n) load_kv((idx + 3) & 3, t + 3);
        cp_wait_rem(n - 1 - idx);
        __syncthreads();

        uint32_t sb = smb + AT_KV0 + (idx & 3)*AT_STAGE;

        // ---- scores (single-pass fp16) ----
        float s[4][4];
        #pragma unroll
        for (int nn = 0; nn < 4; nn++)
            #pragma unroll
            for (int j = 0; j < 4; j++) s[nn][j] = 0.f;

        #pragma unroll
        for (int ks = 0; ks < 8; ks++) {
            uint32_t ah[4];
            uint32_t aoff = sidx(wq + (l & 15), ks*32 + ((l >> 4) << 4), 256);
            ldsm4(ah, smb + aoff);
            #pragma unroll
            for (int ntp = 0; ntp < 2; ntp++) {
                uint32_t bh[4];
                uint32_t boff = sidx(kh*32 + (ntp*2 + ((l >> 4) & 1))*8 + (l & 7),
                                     ks*32 + ((l >> 3) & 1)*16, 256);
                ldsm4(bh, sb + boff);
                mma16816(s[ntp*2],   ah, bh);
                mma16816(s[ntp*2+1], ah, bh + 2);
            }
        }

        // ---- p = exp(s*scale), causal mask, pack fp16 ----
        uint32_t Ph[4][2];
        const bool diag = (t == qt);
        const int lq = q0 + wq + (l >> 2);
        #pragma unroll
        for (int nt = 0; nt < 4; nt++) {
            int kc = t*64 + kh*32 + nt*8 + (l & 3)*2;
            float p00 = __expf(s[nt][0]*SCALE);
            float p01 = __expf(s[nt][1]*SCALE);
            float p10 = __expf(s[nt][2]*SCALE);
            float p11 = __expf(s[nt][3]*SCALE);
            if (diag) {
                if (kc     > lq)     p00 = 0.f;
                if (kc + 1 > lq)     p01 = 0.f;
                if (kc     > lq + 8) p10 = 0.f;
                if (kc + 1 > lq + 8) p11 = 0.f;
            }
            lsum0 += p00 + p01;
            lsum1 += p10 + p11;
            Ph[nt][0] = packh2(p00, p01);
            Ph[nt][1] = packh2(p10, p11);
        }

        // ---- O += P * V (single-pass fp16) ----
        #pragma unroll
        for (int ks = 0; ks < 2; ks++) {
            uint32_t ahh[4] = {Ph[2*ks][0], Ph[2*ks][1], Ph[2*ks+1][0], Ph[2*ks+1][1]};
            #pragma unroll
            for (int ntp = 0; ntp < 8; ntp++) {
                uint32_t bh[4];
                uint32_t boff = sidx(kh*32 + ks*16 + (l & 15),
                                     ntp*32 + ((l >> 4) & 1)*16, 256);
                ldsm4t(bh, sb + 16384 + boff);
                mma16816(o[ntp*2],   ahh, bh);
                mma16816(o[ntp*2+1], ahh, bh + 2);
            }
        }
        __syncthreads();
    }

    // ---- cross-half reduction via smem ----
    if (wid >= 4) {
        float* red = (float*)(sm + AT_KV0) + ((size_t)((wid - 4)*32 + l))*64;
        #pragma unroll
        for (int nt = 0; nt < 16; nt++)
            *(float4*)(red + nt*4) = make_float4(o[nt][0], o[nt][1], o[nt][2], o[nt][3]);
        float* lred = (float*)(sm + AT_KV0 + 32768) + ((wid - 4)*32 + l)*2;
        lred[0] = lsum0; lred[1] = lsum1;
    }
    __syncthreads();
    if (wid < 4) {
        float* red = (float*)(sm + AT_KV0) + ((size_t)(wid*32 + l))*64;
        #pragma unroll
        for (int nt = 0; nt < 16; nt++) {
            float4 r = *(float4*)(red + nt*4);
            o[nt][0] += r.x; o[nt][1] += r.y; o[nt][2] += r.z; o[nt][3] += r.w;
        }
        float* lred = (float*)(sm + AT_KV0 + 32768) + (wid*32 + l)*2;
        lsum0 += lred[0]; lsum1 += lred[1];

        lsum0 += __shfl_xor_sync(0xffffffffu, lsum0, 1);
        lsum0 += __shfl_xor_sync(0xffffffffu, lsum0, 2);
        lsum1 += __shfl_xor_sync(0xffffffffu, lsum1, 1);
        lsum1 += __shfl_xor_sync(0xffffffffu, lsum1, 2);

        const int row0g = q0 + wq + (l >> 2);
        const int cb = (l & 3)*2;
        float* og = out + ((size_t)b*SEQ + row0g)*HEAD;

        if (single) {
            #pragma unroll
            for (int nt = 0; nt < 16; nt++) {
                *(float2*)(og + nt*8 + cb) = make_float2(o[nt][0], o[nt][1]);
                *(float2*)(og + (size_t)8*HEAD + nt*8 + cb) = make_float2(o[nt][2], o[nt][3]);
            }
            if ((l & 3) == 0) {
                g_l[b*SEQ + row0g]     = lsum0;
                g_l[b*SEQ + row0g + 8] = lsum1;
            }
        } else {
            #pragma unroll
            for (int nt = 0; nt < 16; nt++) {
                atomicAdd(og + nt*8 + cb,     o[nt][0]);
                atomicAdd(og + nt*8 + cb + 1, o[nt][1]);
                atomicAdd(og + (size_t)8*HEAD + nt*8 + cb,     o[nt][2]);
                atomicAdd(og + (size_t)8*HEAD + nt*8 + cb + 1, o[nt][3]);
            }
            if ((l & 3) == 0) {
                atomicAdd(g_l + b*SEQ + row0g,     lsum0);
                atomicAdd(g_l + b*SEQ + row0g + 8, lsum1);
            }
        }
    }
}

// ---------------------------------------------------------------------------
extern "C" void kernel_launch(void* const* d_in, const int* in_sizes, int n_in,
                              void* d_out, int out_size)
{
    const float* x  = (const float*)d_in[0];
    const float* Wk = (const float*)d_in[1];
    const float* Wq = (const float*)d_in[2];
    const float* Wv = (const float*)d_in[3];
    float* out = (float*)d_out;

    cudaFuncSetAttribute(proj_kernel, cudaFuncAttributeMaxDynamicSharedMemorySize, PJ_SMEM);
    cudaFuncSetAttribute(attn_kernel, cudaFuncAttributeMaxDynamicSharedMemorySize, AT_SMEM);

    zero_kernel<<<2064, 256>>>(out);
    conv_x_kernel<<<BS*EMBED/1024, 256>>>(x);
    conv_w_kernel<<<dim3(EMBED*HEAD/1024, 3), 256>>>(Wk, Wq, Wv);
    proj_kernel<<<dim3(3, BS/128), 256, PJ_SMEM>>>();
    attn_kernel<<<dim3(64, (SEQ/64 + CHUNK - 1)/CHUNK, BATCH), 256, AT_SMEM>>>(out);
    norm_kernel<<<BS*HEAD/1024, 256>>>(out);
}

// round 9
// speedup vs baseline: 2.1454x; 1.1417x over previous
#include <cuda_runtime.h>
#include <cuda_fp16.h>
#include <cstdint>

#define EMBED 1024
#define HEAD  128
#define BATCH 4
#define SEQ   4096
#define BS    (BATCH*SEQ)
#define SCALE 0.03125f   // 1/sqrt(1024)

// ---------------------------------------------------------------------------
// Global scratch: everything single fp16 (11-bit mantissa covers 1e-3 budget)
// ---------------------------------------------------------------------------
__device__ __align__(256) __half g_x[BS*EMBED];
__device__ __align__(256) __half g_w[3*EMBED*HEAD];
__device__ __align__(256) __half g_q[BS*HEAD], g_k[BS*HEAD], g_v[BS*HEAD];
__device__ __align__(256) float g_l[BS];

// ---------------------------------------------------------------------------
// helpers
// ---------------------------------------------------------------------------
__device__ __forceinline__ uint32_t smem_u32(const void* p) {
    uint32_t a;
    asm("{ .reg .u64 t; cvta.to.shared.u64 t, %1; cvt.u32.u64 %0, t; }" : "=r"(a) : "l"(p));
    return a;
}
__device__ __forceinline__ uint32_t sidx(int row, int cb, int rb) {
    return (uint32_t)(row*rb + ((((cb >> 4) ^ (row & 7)) << 4) | (cb & 15)));
}
__device__ __forceinline__ void cpa(uint32_t d, const void* s) {
    asm volatile("cp.async.cg.shared.global [%0], [%1], 16;" :: "r"(d), "l"(s));
}
#define CP_COMMIT() asm volatile("cp.async.commit_group;" ::: "memory")
#define CP_WAIT0()  asm volatile("cp.async.wait_group 0;" ::: "memory")
#define CP_WAIT1()  asm volatile("cp.async.wait_group 1;" ::: "memory")
#define CP_WAIT2()  asm volatile("cp.async.wait_group 2;" ::: "memory")
// 3-stage ring: allow at most `rem` groups in flight (max 2)
__device__ __forceinline__ void cp_wait_rem2(int rem) {
    if (rem >= 2)      CP_WAIT2();
    else if (rem == 1) CP_WAIT1();
    else               CP_WAIT0();
}

__device__ __forceinline__ void ldsm4(uint32_t* r, uint32_t a) {
    asm volatile("ldmatrix.sync.aligned.m8n8.x4.shared.b16 {%0,%1,%2,%3}, [%4];"
        : "=r"(r[0]), "=r"(r[1]), "=r"(r[2]), "=r"(r[3]) : "r"(a));
}
__device__ __forceinline__ void ldsm4t(uint32_t* r, uint32_t a) {
    asm volatile("ldmatrix.sync.aligned.m8n8.x4.trans.shared.b16 {%0,%1,%2,%3}, [%4];"
        : "=r"(r[0]), "=r"(r[1]), "=r"(r[2]), "=r"(r[3]) : "r"(a));
}
__device__ __forceinline__ void mma16816(float* d, const uint32_t* a, const uint32_t* b) {
    asm volatile("mma.sync.aligned.m16n8k16.row.col.f32.f16.f16.f32 "
        "{%0,%1,%2,%3}, {%4,%5,%6,%7}, {%8,%9}, {%0,%1,%2,%3};"
        : "+f"(d[0]), "+f"(d[1]), "+f"(d[2]), "+f"(d[3])
        : "r"(a[0]), "r"(a[1]), "r"(a[2]), "r"(a[3]), "r"(b[0]), "r"(b[1]));
}
__device__ __forceinline__ uint32_t packh2(float a, float b) {
    __half2 h = __floats2half2_rn(a, b);
    return *(uint32_t*)&h;
}

// ---------------------------------------------------------------------------
// convert kernels: fp32 -> fp16
// ---------------------------------------------------------------------------
__global__ __launch_bounds__(256) void conv_x_kernel(const float* __restrict__ x)
{
    size_t i = ((size_t)blockIdx.x*256 + threadIdx.x)*4;
    float4 v = *(const float4*)(x + i);
    *(uint2*)(g_x + i) = make_uint2(packh2(v.x, v.y), packh2(v.z, v.w));
}
__global__ __launch_bounds__(256) void conv_w_kernel(
    const float* __restrict__ Wk, const float* __restrict__ Wq, const float* __restrict__ Wv)
{
    const int w = blockIdx.y;
    const float* W = (w == 0) ? Wq : (w == 1) ? Wk : Wv;
    size_t base = (size_t)w*EMBED*HEAD;
    size_t i = ((size_t)blockIdx.x*256 + threadIdx.x)*4;
    float4 v = *(const float4*)(W + i);
    *(uint2*)(g_w + base + i) = make_uint2(packh2(v.x, v.y), packh2(v.z, v.w));
}

// ---------------------------------------------------------------------------
// zero / normalize
// ---------------------------------------------------------------------------
__global__ __launch_bounds__(256) void zero_kernel(float* __restrict__ out)
{
    int bid = blockIdx.x;
    if (bid < 2048) {
        size_t i = ((size_t)bid*256 + threadIdx.x)*4;
        *(float4*)(out + i) = make_float4(0.f, 0.f, 0.f, 0.f);
    } else {
        size_t i = ((size_t)(bid - 2048)*256 + threadIdx.x)*4;
        *(float4*)(g_l + i) = make_float4(0.f, 0.f, 0.f, 0.f);
    }
}
__global__ __launch_bounds__(256) void norm_kernel(float* __restrict__ out)
{
    size_t i4 = (size_t)blockIdx.x*256 + threadIdx.x;
    int row = (int)(i4 >> 5);
    float inv = 1.f / g_l[row];
    float4 v = *(float4*)(out + i4*4);
    v.x *= inv; v.y *= inv; v.z *= inv; v.w *= inv;
    *(float4*)(out + i4*4) = v;
}

// ---------------------------------------------------------------------------
// Projection GEMM, fp16 single-pass, 3-stage cp.async ring, 2 CTAs/SM.
// 256 threads, warp tile 32 rows x 64 cols.
// stage = X 16K | W 16K (32KB); 3 stages = 96KB -> 2 CTAs/SM.
// ---------------------------------------------------------------------------
#define PJ_STAGE 32768
#define PJ_SMEM  (3*PJ_STAGE)

__global__ __launch_bounds__(256, 2) void proj_kernel()
{
    extern __shared__ char sm[];
    const uint32_t smb = smem_u32(sm);
    const int tid = threadIdx.x, wid = tid >> 5, l = tid & 31;
    const int w = blockIdx.x;
    const int row0 = blockIdx.y * 128;
    const int rg = wid & 3;
    const int ch = wid >> 2;

    const __half* xg = g_x + (size_t)row0*EMBED;
    const __half* wg = g_w + (size_t)w*EMBED*HEAD;

    auto load_stage = [&](int s, int k0) {
        uint32_t sb = smb + s*PJ_STAGE;
        #pragma unroll
        for (int i = 0; i < 4; i++) {               // x tile [128][64]
            int f = i*256 + tid;
            int r = f >> 3, c = f & 7;
            cpa(sb + sidx(r, c*16, 128), xg + (size_t)r*EMBED + k0 + c*8);
        }
        #pragma unroll
        for (int i = 0; i < 4; i++) {               // W tile [64][128]
            int f = i*256 + tid;
            int r = f >> 4, c = f & 15;
            cpa(sb + 16384 + sidx(r, c*16, 256), wg + (size_t)(k0 + r)*HEAD + c*8);
        }
        CP_COMMIT();
    };

    float acc[2][8][4];
    #pragma unroll
    for (int m = 0; m < 2; m++)
        #pragma unroll
        for (int n = 0; n < 8; n++)
            #pragma unroll
            for (int j = 0; j < 4; j++) acc[m][n][j] = 0.f;

    load_stage(0, 0);
    load_stage(1, 64);

    int stage = 0, nstage = 2 % 3;
    for (int chk = 0; chk < 16; chk++) {
        if (chk + 2 < 16) { load_stage(nstage, (chk + 2)*64); nstage = (nstage + 1 == 3) ? 0 : nstage + 1; }
        cp_wait_rem2(15 - chk);
        __syncthreads();

        uint32_t sb = smb + stage*PJ_STAGE;
        stage = (stage + 1 == 3) ? 0 : stage + 1;
        #pragma unroll
        for (int ks = 0; ks < 4; ks++) {
            uint32_t ah[2][4];
            #pragma unroll
            for (int m = 0; m < 2; m++) {
                uint32_t aoff = sidx(rg*32 + m*16 + (l & 15), ks*32 + ((l >> 4) << 4), 128);
                ldsm4(ah[m], sb + aoff);
            }
            #pragma unroll
            for (int np = 0; np < 4; np++) {
                uint32_t bh[4];
                uint32_t boff = sidx(ks*16 + (l & 15),
                                     ch*128 + np*32 + ((l >> 4) & 1)*16, 256);
                ldsm4t(bh, sb + 16384 + boff);
                #pragma unroll
                for (int m = 0; m < 2; m++) {
                    mma16816(acc[m][np*2],   ah[m], bh);
                    mma16816(acc[m][np*2+1], ah[m], bh + 2);
                }
            }
        }
        __syncthreads();
    }

    __half* dst = (w == 0) ? g_q : (w == 1) ? g_k : g_v;
    #pragma unroll
    for (int m = 0; m < 2; m++) {
        const int g0 = row0 + rg*32 + m*16 + (l >> 2);
        const int cb = ch*64 + (l & 3)*2;
        #pragma unroll
        for (int nt = 0; nt < 8; nt++) {
            *(uint32_t*)(dst + (size_t)g0*HEAD + cb + nt*8) =
                packh2(acc[m][nt][0], acc[m][nt][1]);
            *(uint32_t*)(dst + (size_t)(g0 + 8)*HEAD + cb + nt*8) =
                packh2(acc[m][nt][2], acc[m][nt][3]);
        }
    }
}

// ---------------------------------------------------------------------------
// Flash attention: fp16 single-pass, 3-stage KV ring, 2 CTAs/SM.
// 8 warps, 64 queries, keys split across warp halves, split-KV CHUNK=32.
// smem: Q 16K | 3 x stage{K 16K, V 16K} = 112KB -> 2 CTAs/SM.
// ---------------------------------------------------------------------------
#define AT_KV0   16384
#define AT_STAGE 32768
#define AT_SMEM  (AT_KV0 + 3*AT_STAGE)
#define CHUNK    32

__global__ __launch_bounds__(256, 2) void attn_kernel(float* __restrict__ out)
{
    const int qt = 63 - blockIdx.x;
    const int c  = blockIdx.y;
    const int t0 = c*CHUNK;
    const int t1 = min(t0 + CHUNK, qt + 1);
    if (t0 >= t1) return;

    extern __shared__ char sm[];
    const uint32_t smb = smem_u32(sm);
    const int tid = threadIdx.x, wid = tid >> 5, l = tid & 31;
    const int b   = blockIdx.z;
    const int q0  = qt*64;
    const int wq  = (wid & 3)*16;
    const int kh  = wid >> 2;
    const bool single = (c == 0) && (qt + 1 <= CHUNK);
    const int n = t1 - t0;

    // Q tile (persistent) — joins group 0 (first load_kv commit)
    {
        const __half* qg = g_q + ((size_t)b*SEQ + q0)*HEAD;
        #pragma unroll
        for (int i = 0; i < 4; i++) {
            int f = i*256 + tid;
            int r = f >> 4, cc = f & 15;
            cpa(smb + sidx(r, cc*16, 256), qg + (size_t)r*HEAD + cc*8);
        }
    }

    auto load_kv = [&](int s, int t) {
        uint32_t sb = smb + AT_KV0 + s*AT_STAGE;
        const size_t base = ((size_t)b*SEQ + t*64)*HEAD;
        #pragma unroll
        for (int i = 0; i < 4; i++) {
            int f = i*256 + tid;
            int r = f >> 4, cc = f & 15;
            uint32_t d = sb + sidx(r, cc*16, 256);
            const size_t g = base + (size_t)r*HEAD + cc*8;
            cpa(d,         g_k + g);
            cpa(d + 16384, g_v + g);
        }
        CP_COMMIT();
    };

    float o[16][4];
    #pragma unroll
    for (int nn = 0; nn < 16; nn++)
        #pragma unroll
        for (int j = 0; j < 4; j++) o[nn][j] = 0.f;
    float lsum0 = 0.f, lsum1 = 0.f;

    const int pf = (n < 2) ? n : 2;
    for (int i = 0; i < pf; i++) load_kv(i, t0 + i);

    int stage = 0, nstage = pf % 3;
    for (int t = t0; t < t1; t++) {
        const int idx = t - t0;
        if (idx + 2 < n) { load_kv(nstage, t + 2); nstage = (nstage + 1 == 3) ? 0 : nstage + 1; }
        cp_wait_rem2(n - 1 - idx);
        __syncthreads();

        uint32_t sb = smb + AT_KV0 + stage*AT_STAGE;
        stage = (stage + 1 == 3) ? 0 : stage + 1;

        // ---- scores (single-pass fp16) ----
        float s[4][4];
        #pragma unroll
        for (int nn = 0; nn < 4; nn++)
            #pragma unroll
            for (int j = 0; j < 4; j++) s[nn][j] = 0.f;

        #pragma unroll
        for (int ks = 0; ks < 8; ks++) {
            uint32_t ah[4];
            uint32_t aoff = sidx(wq + (l & 15), ks*32 + ((l >> 4) << 4), 256);
            ldsm4(ah, smb + aoff);
            #pragma unroll
            for (int ntp = 0; ntp < 2; ntp++) {
                uint32_t bh[4];
                uint32_t boff = sidx(kh*32 + (ntp*2 + ((l >> 4) & 1))*8 + (l & 7),
                                     ks*32 + ((l >> 3) & 1)*16, 256);
                ldsm4(bh, sb + boff);
                mma16816(s[ntp*2],   ah, bh);
                mma16816(s[ntp*2+1], ah, bh + 2);
            }
        }

        // ---- p = exp(s*scale), causal mask, pack fp16 ----
        uint32_t Ph[4][2];
        const bool diag = (t == qt);
        const int lq = q0 + wq + (l >> 2);
        #pragma unroll
        for (int nt = 0; nt < 4; nt++) {
            int kc = t*64 + kh*32 + nt*8 + (l & 3)*2;
            float p00 = __expf(s[nt][0]*SCALE);
            float p01 = __expf(s[nt][1]*SCALE);
            float p10 = __expf(s[nt][2]*SCALE);
            float p11 = __expf(s[nt][3]*SCALE);
            if (diag) {
                if (kc     > lq)     p00 = 0.f;
                if (kc + 1 > lq)     p01 = 0.f;
                if (kc     > lq + 8) p10 = 0.f;
                if (kc + 1 > lq + 8) p11 = 0.f;
            }
            lsum0 += p00 + p01;
            lsum1 += p10 + p11;
            Ph[nt][0] = packh2(p00, p01);
            Ph[nt][1] = packh2(p10, p11);
        }

        // ---- O += P * V (single-pass fp16) ----
        #pragma unroll
        for (int ks = 0; ks < 2; ks++) {
            uint32_t ahh[4] = {Ph[2*ks][0], Ph[2*ks][1], Ph[2*ks+1][0], Ph[2*ks+1][1]};
            #pragma unroll
            for (int ntp = 0; ntp < 8; ntp++) {
                uint32_t bh[4];
                uint32_t boff = sidx(kh*32 + ks*16 + (l & 15),
                                     ntp*32 + ((l >> 4) & 1)*16, 256);
                ldsm4t(bh, sb + 16384 + boff);
                mma16816(o[ntp*2],   ahh, bh);
                mma16816(o[ntp*2+1], ahh, bh + 2);
            }
        }
        __syncthreads();
    }

    // ---- cross-half reduction via smem ----
    if (wid >= 4) {
        float* red = (float*)(sm + AT_KV0) + ((size_t)((wid - 4)*32 + l))*64;
        #pragma unroll
        for (int nt = 0; nt < 16; nt++)
            *(float4*)(red + nt*4) = make_float4(o[nt][0], o[nt][1], o[nt][2], o[nt][3]);
        float* lred = (float*)(sm + AT_KV0 + 32768) + ((wid - 4)*32 + l)*2;
        lred[0] = lsum0; lred[1] = lsum1;
    }
    __syncthreads();
    if (wid < 4) {
        float* red = (float*)(sm + AT_KV0) + ((size_t)(wid*32 + l))*64;
        #pragma unroll
        for (int nt = 0; nt < 16; nt++) {
            float4 r = *(float4*)(red + nt*4);
            o[nt][0] += r.x; o[nt][1] += r.y; o[nt][2] += r.z; o[nt][3] += r.w;
        }
        float* lred = (float*)(sm + AT_KV0 + 32768) + (wid*32 + l)*2;
        lsum0 += lred[0]; lsum1 += lred[1];

        lsum0 += __shfl_xor_sync(0xffffffffu, lsum0, 1);
        lsum0 += __shfl_xor_sync(0xffffffffu, lsum0, 2);
        lsum1 += __shfl_xor_sync(0xffffffffu, lsum1, 1);
        lsum1 += __shfl_xor_sync(0xffffffffu, lsum1, 2);

        const int row0g = q0 + wq + (l >> 2);
        const int cb = (l & 3)*2;
        float* og = out + ((size_t)b*SEQ + row0g)*HEAD;

        if (single) {
            #pragma unroll
            for (int nt = 0; nt < 16; nt++) {
                *(float2*)(og + nt*8 + cb) = make_float2(o[nt][0], o[nt][1]);
                *(float2*)(og + (size_t)8*HEAD + nt*8 + cb) = make_float2(o[nt][2], o[nt][3]);
            }
            if ((l & 3) == 0) {
                g_l[b*SEQ + row0g]     = lsum0;
                g_l[b*SEQ + row0g + 8] = lsum1;
            }
        } else {
            #pragma unroll
            for (int nt = 0; nt < 16; nt++) {
                atomicAdd(og + nt*8 + cb,     o[nt][0]);
                atomicAdd(og + nt*8 + cb + 1, o[nt][1]);
                atomicAdd(og + (size_t)8*HEAD + nt*8 + cb,     o[nt][2]);
                atomicAdd(og + (size_t)8*HEAD + nt*8 + cb + 1, o[nt][3]);
            }
            if ((l & 3) == 0) {
                atomicAdd(g_l + b*SEQ + row0g,     lsum0);
                atomicAdd(g_l + b*SEQ + row0g + 8, lsum1);
            }
        }
    }
}

// ---------------------------------------------------------------------------
extern "C" void kernel_launch(void* const* d_in, const int* in_sizes, int n_in,
                              void* d_out, int out_size)
{
    const float* x  = (const float*)d_in[0];
    const float* Wk = (const float*)d_in[1];
    const float* Wq = (const float*)d_in[2];
    const float* Wv = (const float*)d_in[3];
    float* out = (float*)d_out;

    cudaFuncSetAttribute(proj_kernel, cudaFuncAttributeMaxDynamicSharedMemorySize, PJ_SMEM);
    cudaFuncSetAttribute(attn_kernel, cudaFuncAttributeMaxDynamicSharedMemorySize, AT_SMEM);

    zero_kernel<<<2064, 256>>>(out);
    conv_x_kernel<<<BS*EMBED/1024, 256>>>(x);
    conv_w_kernel<<<dim3(EMBED*HEAD/1024, 3), 256>>>(Wk, Wq, Wv);
    proj_kernel<<<dim3(3, BS/128), 256, PJ_SMEM>>>();
    attn_kernel<<<dim3(64, (SEQ/64 + CHUNK - 1)/CHUNK, BATCH), 256, AT_SMEM>>>(out);
    norm_kernel<<<BS*HEAD/1024, 256>>>(out);
}